// round 2
// baseline (speedup 1.0000x reference)
#include <cuda_runtime.h>

#define LL 320
#define DD 128
#define NH 4
#define DH 32
#define NR (LL*LL)

// Scratch (static device globals; no runtime allocation allowed)
__device__ float g_Q[NR*DD];
__device__ float g_K[NR*DD];
__device__ float g_V[NR*DD];
__device__ float g_G[NR*DD];
__device__ float g_Bb[LL*NH*LL];   // bias[i][h][j]
__device__ float g_A[NR*DD];       // gated attention output (pre-Wo)

// ---------------------------------------------------------------------------
// Kernel 1: LayerNorm + {Q,K,V,G} projections + attention bias (raw pair @ Wb^T)
// Block: 256 threads, 64 rows of the (102400 x 128) matrix per block.
// ---------------------------------------------------------------------------
__global__ void __launch_bounds__(256) ln_proj_kernel(
    const float* __restrict__ pair, const float* __restrict__ nw, const float* __restrict__ nb,
    const float* __restrict__ Wq, const float* __restrict__ Wk, const float* __restrict__ Wv,
    const float* __restrict__ Wg, const float* __restrict__ bg, const float* __restrict__ Wb)
{
    extern __shared__ float sm[];
    float* xs  = sm;                  // 64*128 normalized rows
    float* WT  = sm + 64*DD;          // 128*129 transposed weight (pad avoids bank conflicts)
    float* Wbs = WT + 128*129;        // 4*128
    float* nws = Wbs + 4*128;         // 128
    float* nbs = nws + 128;           // 128

    int tid  = threadIdx.x;
    int warp = tid >> 5, lane = tid & 31;
    int r0   = blockIdx.x * 64;

    for (int idx = tid; idx < 4*128; idx += 256) Wbs[idx] = Wb[idx];
    if (tid < 128) { nws[tid] = nw[tid]; nbs[tid] = nb[tid]; }
    __syncthreads();

    // Phase A: LayerNorm (one warp per row, 8 rows/warp) + bias projection from RAW pair
    for (int rr = warp; rr < 64; rr += 8) {
        int r = r0 + rr;
        int d0 = lane * 4;
        float4 v = *(const float4*)(pair + (size_t)r*DD + d0);
        float s  = v.x + v.y + v.z + v.w;
        float ss = v.x*v.x + v.y*v.y + v.z*v.z + v.w*v.w;
        #pragma unroll
        for (int o = 16; o; o >>= 1) {
            s  += __shfl_xor_sync(0xffffffffu, s,  o);
            ss += __shfl_xor_sync(0xffffffffu, ss, o);
        }
        float mu   = s * (1.0f/128.0f);
        float var  = ss * (1.0f/128.0f) - mu*mu;
        float rstd = rsqrtf(var + 1e-5f);
        xs[rr*DD + d0+0] = (v.x-mu)*rstd*nws[d0+0] + nbs[d0+0];
        xs[rr*DD + d0+1] = (v.y-mu)*rstd*nws[d0+1] + nbs[d0+1];
        xs[rr*DD + d0+2] = (v.z-mu)*rstd*nws[d0+2] + nbs[d0+2];
        xs[rr*DD + d0+3] = (v.w-mu)*rstd*nws[d0+3] + nbs[d0+3];
        #pragma unroll
        for (int h = 0; h < NH; h++) {
            const float* wb = Wbs + h*128 + d0;
            float p = v.x*wb[0] + v.y*wb[1] + v.z*wb[2] + v.w*wb[3];
            #pragma unroll
            for (int o = 16; o; o >>= 1) p += __shfl_xor_sync(0xffffffffu, p, o);
            if (lane == 0) g_Bb[((r/LL)*NH + h)*LL + (r % LL)] = p;
        }
    }

    // Phase B: 4 GEMMs, 64x128 output tile each; thread = (col, row-half), RB=32 rows
    int c  = tid & 127;
    int rh = tid >> 7;
    int rb = rh * 32;
    const float* Ws[4] = {Wq, Wk, Wv, Wg};
    #pragma unroll 1
    for (int m = 0; m < 4; m++) {
        __syncthreads();
        const float* W = Ws[m];
        for (int idx = tid; idx < DD*DD; idx += 256) {
            int j = idx >> 7, d = idx & 127;
            WT[d*129 + j] = W[idx];
        }
        __syncthreads();
        float acc[32];
        #pragma unroll
        for (int r = 0; r < 32; r++) acc[r] = 0.f;
        for (int d = 0; d < DD; d++) {
            float w = WT[d*129 + c];
            #pragma unroll
            for (int r = 0; r < 32; r++) acc[r] = fmaf(xs[(rb+r)*DD + d], w, acc[r]);
        }
        float* outp = (m==0) ? g_Q : (m==1) ? g_K : (m==2) ? g_V : g_G;
        float bgc = (m==3) ? bg[c] : 0.f;
        #pragma unroll
        for (int r = 0; r < 32; r++) {
            float val = acc[r] + bgc;
            if (m == 3) val = 1.f/(1.f + __expf(-val));
            outp[(size_t)(r0 + rb + r)*DD + c] = val;
        }
    }
}

// ---------------------------------------------------------------------------
// Kernel 2: attention per (i, h). softmax(QK^T*scale + bias) V, gated by g.
// Block: 256 threads = 32 queries x 8-thread key groups.
// ---------------------------------------------------------------------------
__global__ void __launch_bounds__(256) attn_kernel()
{
    extern __shared__ float sm[];
    float* Ks = sm;                   // 320*36 (pad 36: float4-aligned, conflict-free)
    float* Vs = Ks + LL*36;           // 320*36
    float* Ps = Vs + LL*36;           // 32*321 probabilities
    float* bs = Ps + 32*321;          // 320

    int h = blockIdx.x, i = blockIdx.y;
    int tid = threadIdx.x;
    size_t rowbase = ((size_t)i * LL) * DD + h * DH;

    for (int idx = tid; idx < LL*DH; idx += 256) {
        int j = idx >> 5, d = idx & 31;
        Ks[j*36 + d] = g_K[rowbase + (size_t)j*DD + d];
        Vs[j*36 + d] = g_V[rowbase + (size_t)j*DD + d];
    }
    for (int idx = tid; idx < LL; idx += 256) bs[idx] = g_Bb[(i*NH + h)*LL + idx];
    __syncthreads();

    int q = tid >> 3, kg = tid & 7;
    const float scale = 0.17677669529663687f;  // 1/sqrt(32)

    #pragma unroll 1
    for (int t = 0; t < 10; t++) {
        // Load this group's query row straight into registers (8 threads x 4 floats,
        // shuffled to all 32): each thread reads its own 16B chunk, coalesced.
        float qreg[32];
        {
            const float* qp = g_Q + rowbase + (size_t)(t*32 + q)*DD;
            float4 qv = *(const float4*)(qp + kg*4);
            #pragma unroll
            for (int g8 = 0; g8 < 8; g8++) {
                qreg[g8*4+0] = __shfl_sync(0xffffffffu, qv.x, (q&3)*8 + g8, 32);
                qreg[g8*4+1] = __shfl_sync(0xffffffffu, qv.y, (q&3)*8 + g8, 32);
                qreg[g8*4+2] = __shfl_sync(0xffffffffu, qv.z, (q&3)*8 + g8, 32);
                qreg[g8*4+3] = __shfl_sync(0xffffffffu, qv.w, (q&3)*8 + g8, 32);
            }
        }

        // scores: this thread owns keys k = kg + 8*kk, kk in [0,40)
        float sc[40];
        #pragma unroll 4
        for (int kk = 0; kk < 40; kk++) {
            int k = kg + kk*8;
            float a = 0.f;
            #pragma unroll
            for (int d4 = 0; d4 < 8; d4++) {
                float4 kv = *(const float4*)(Ks + k*36 + d4*4);
                a = fmaf(qreg[d4*4+0], kv.x, a);
                a = fmaf(qreg[d4*4+1], kv.y, a);
                a = fmaf(qreg[d4*4+2], kv.z, a);
                a = fmaf(qreg[d4*4+3], kv.w, a);
            }
            sc[kk] = a*scale + bs[k];
        }
        // softmax across the 8-thread q-group
        float mx = -1e30f;
        #pragma unroll
        for (int kk = 0; kk < 40; kk++) mx = fmaxf(mx, sc[kk]);
        #pragma unroll
        for (int o = 4; o; o >>= 1) mx = fmaxf(mx, __shfl_xor_sync(0xffffffffu, mx, o));
        float sum = 0.f;
        #pragma unroll
        for (int kk = 0; kk < 40; kk++) { sc[kk] = __expf(sc[kk] - mx); sum += sc[kk]; }
        #pragma unroll
        for (int o = 4; o; o >>= 1) sum += __shfl_xor_sync(0xffffffffu, sum, o);
        float inv = 1.f / sum;
        #pragma unroll
        for (int kk = 0; kk < 40; kk++) Ps[q*321 + kg + kk*8] = sc[kk] * inv;
        __syncwarp();

        // PV: thread computes dh = kg*4 .. kg*4+3 over all 320 keys
        float4 o4 = make_float4(0.f, 0.f, 0.f, 0.f);
        int dd = kg * 4;
        for (int k = 0; k < LL; k++) {
            float p = Ps[q*321 + k];
            float4 v4 = *(const float4*)(Vs + k*36 + dd);
            o4.x = fmaf(p, v4.x, o4.x);
            o4.y = fmaf(p, v4.y, o4.y);
            o4.z = fmaf(p, v4.z, o4.z);
            o4.w = fmaf(p, v4.w, o4.w);
        }
        size_t ob = rowbase + (size_t)(t*32 + q)*DD + dd;
        float4 gv = *(const float4*)(g_G + ob);
        float4 res = make_float4(o4.x*gv.x, o4.y*gv.y, o4.z*gv.z, o4.w*gv.w);
        *(float4*)(g_A + ob) = res;
    }
}

// ---------------------------------------------------------------------------
// Kernel 3: out = pair + att @ Wo^T + bo
// ---------------------------------------------------------------------------
__global__ void __launch_bounds__(256) oproj_kernel(
    const float* __restrict__ pair, const float* __restrict__ Wo,
    const float* __restrict__ bo, float* __restrict__ out)
{
    extern __shared__ float sm[];
    float* xs = sm;             // 64*128
    float* WT = sm + 64*DD;     // 128*129

    int tid = threadIdx.x;
    int r0  = blockIdx.x * 64;

    for (int idx = tid; idx < 64*32; idx += 256) {
        int rr = idx >> 5, dd = (idx & 31) * 4;
        *(float4*)(xs + rr*DD + dd) = *(const float4*)(g_A + (size_t)(r0+rr)*DD + dd);
    }
    for (int idx = tid; idx < DD*DD; idx += 256) {
        int j = idx >> 7, d = idx & 127;
        WT[d*129 + j] = Wo[idx];
    }
    __syncthreads();

    int c = tid & 127, rh = tid >> 7, rb = rh * 32;
    float acc[32];
    #pragma unroll
    for (int r = 0; r < 32; r++) acc[r] = 0.f;
    for (int d = 0; d < DD; d++) {
        float w = WT[d*129 + c];
        #pragma unroll
        for (int r = 0; r < 32; r++) acc[r] = fmaf(xs[(rb+r)*DD + d], w, acc[r]);
    }
    float boc = bo[c];
    #pragma unroll
    for (int r = 0; r < 32; r++) {
        size_t gi = (size_t)(r0 + rb + r)*DD + c;
        out[gi] = pair[gi] + boc + acc[r];
    }
}

// ---------------------------------------------------------------------------
extern "C" void kernel_launch(void* const* d_in, const int* in_sizes, int n_in,
                              void* d_out, int out_size)
{
    const float* pair = (const float*)d_in[0];
    const float* nw   = (const float*)d_in[1];
    const float* nb   = (const float*)d_in[2];
    const float* Wq   = (const float*)d_in[3];
    const float* Wk   = (const float*)d_in[4];
    const float* Wv   = (const float*)d_in[5];
    const float* Wg   = (const float*)d_in[6];
    const float* bg   = (const float*)d_in[7];
    const float* Wo   = (const float*)d_in[8];
    const float* bo   = (const float*)d_in[9];
    const float* Wb   = (const float*)d_in[10];
    float* out = (float*)d_out;

    size_t sm1 = (size_t)(64*DD + 128*129 + 4*128 + 256) * sizeof(float);   // ~101.9 KB
    size_t sm2 = (size_t)(LL*36*2 + 32*321 + LL) * sizeof(float);           // ~134.5 KB
    size_t sm3 = (size_t)(64*DD + 128*129) * sizeof(float);                 // ~98.8 KB

    cudaFuncSetAttribute(ln_proj_kernel, cudaFuncAttributeMaxDynamicSharedMemorySize, (int)sm1);
    cudaFuncSetAttribute(attn_kernel,    cudaFuncAttributeMaxDynamicSharedMemorySize, (int)sm2);
    cudaFuncSetAttribute(oproj_kernel,   cudaFuncAttributeMaxDynamicSharedMemorySize, (int)sm3);

    ln_proj_kernel<<<NR/64, 256, sm1>>>(pair, nw, nb, Wq, Wk, Wv, Wg, bg, Wb);
    attn_kernel<<<dim3(NH, LL), 256, sm2>>>();
    oproj_kernel<<<NR/64, 256, sm3>>>(pair, Wo, bo, out);
}

// round 4
// speedup vs baseline: 1.3370x; 1.3370x over previous
#include <cuda_runtime.h>

#define LL 320
#define DD 128
#define NH 4
#define DH 32
#define NR (LL*LL)

// Scratch (static device globals; no runtime allocation allowed)
__device__ float g_Q[NR*DD];
__device__ float g_K[NR*DD];
__device__ float g_V[NR*DD];
__device__ float g_G[NR*DD];
__device__ float g_Bb[LL*NH*LL];   // bias[i][h][j]
__device__ float g_A[NR*DD];       // gated attention output (pre-Wo)

// ---------------------------------------------------------------------------
// Kernel 1: LayerNorm + {Q,K,V,G} projections + attention bias (raw pair @ Wb^T)
// 256 threads, 64 rows per block. GEMM: 2D register tiling 4 rows x 8 cols.
// ---------------------------------------------------------------------------
__global__ void __launch_bounds__(256) ln_proj_kernel(
    const float* __restrict__ pair, const float* __restrict__ nw, const float* __restrict__ nb,
    const float* __restrict__ Wq, const float* __restrict__ Wk, const float* __restrict__ Wv,
    const float* __restrict__ Wg, const float* __restrict__ bg, const float* __restrict__ Wb)
{
    extern __shared__ float sm[];
    float* xs  = sm;                  // 64*128 = 8192
    float* WT  = sm + 8192;           // 128*132 = 16896 (pad 132: 16B-aligned rows)
    float* Wbs = WT + 16896;          // 512
    float* nws = Wbs + 512;           // 128
    float* nbs = nws + 128;           // 128

    int tid  = threadIdx.x;
    int warp = tid >> 5, lane = tid & 31;
    int r0   = blockIdx.x * 64;

    for (int idx = tid; idx < 4*128; idx += 256) Wbs[idx] = Wb[idx];
    if (tid < 128) { nws[tid] = nw[tid]; nbs[tid] = nb[tid]; }
    __syncthreads();

    // Phase A: LayerNorm (warp per row) + bias projection from RAW pair
    for (int rr = warp; rr < 64; rr += 8) {
        int r = r0 + rr;
        int d0 = lane * 4;
        float4 v = *(const float4*)(pair + (size_t)r*DD + d0);
        float s  = v.x + v.y + v.z + v.w;
        float ss = v.x*v.x + v.y*v.y + v.z*v.z + v.w*v.w;
        #pragma unroll
        for (int o = 16; o; o >>= 1) {
            s  += __shfl_xor_sync(0xffffffffu, s,  o);
            ss += __shfl_xor_sync(0xffffffffu, ss, o);
        }
        float mu   = s * (1.0f/128.0f);
        float var  = ss * (1.0f/128.0f) - mu*mu;
        float rstd = rsqrtf(var + 1e-5f);
        xs[rr*DD + d0+0] = (v.x-mu)*rstd*nws[d0+0] + nbs[d0+0];
        xs[rr*DD + d0+1] = (v.y-mu)*rstd*nws[d0+1] + nbs[d0+1];
        xs[rr*DD + d0+2] = (v.z-mu)*rstd*nws[d0+2] + nbs[d0+2];
        xs[rr*DD + d0+3] = (v.w-mu)*rstd*nws[d0+3] + nbs[d0+3];
        #pragma unroll
        for (int h = 0; h < NH; h++) {
            const float* wb = Wbs + h*128 + d0;
            float p = v.x*wb[0] + v.y*wb[1] + v.z*wb[2] + v.w*wb[3];
            #pragma unroll
            for (int o = 16; o; o >>= 1) p += __shfl_xor_sync(0xffffffffu, p, o);
            if (lane == 0) g_Bb[((r/LL)*NH + h)*LL + (r % LL)] = p;
        }
    }

    // Phase B: 4 GEMMs; thread tile = 4 rows x 8 cols
    int tx = tid & 15, ty = tid >> 4;      // tx: col group (8 cols), ty: row group (4 rows)
    const float4* WT4 = (const float4*)WT;
    const float* Ws[4] = {Wq, Wk, Wv, Wg};
    #pragma unroll 1
    for (int m = 0; m < 4; m++) {
        __syncthreads();
        const float* W = Ws[m];
        for (int idx = tid; idx < DD*DD; idx += 256) {
            int j = idx >> 7, d = idx & 127;
            WT[d*132 + j] = W[idx];
        }
        __syncthreads();
        float acc[4][8];
        #pragma unroll
        for (int j = 0; j < 4; j++)
            #pragma unroll
            for (int c = 0; c < 8; c++) acc[j][c] = 0.f;
        const float* xr0 = xs + (ty*4+0)*DD;
        const float* xr1 = xs + (ty*4+1)*DD;
        const float* xr2 = xs + (ty*4+2)*DD;
        const float* xr3 = xs + (ty*4+3)*DD;
        #pragma unroll 4
        for (int d = 0; d < DD; d++) {
            float4 wa = WT4[d*33 + tx*2];
            float4 wb = WT4[d*33 + tx*2 + 1];
            float x0 = xr0[d], x1 = xr1[d], x2 = xr2[d], x3 = xr3[d];
            acc[0][0] = fmaf(x0, wa.x, acc[0][0]); acc[0][1] = fmaf(x0, wa.y, acc[0][1]);
            acc[0][2] = fmaf(x0, wa.z, acc[0][2]); acc[0][3] = fmaf(x0, wa.w, acc[0][3]);
            acc[0][4] = fmaf(x0, wb.x, acc[0][4]); acc[0][5] = fmaf(x0, wb.y, acc[0][5]);
            acc[0][6] = fmaf(x0, wb.z, acc[0][6]); acc[0][7] = fmaf(x0, wb.w, acc[0][7]);
            acc[1][0] = fmaf(x1, wa.x, acc[1][0]); acc[1][1] = fmaf(x1, wa.y, acc[1][1]);
            acc[1][2] = fmaf(x1, wa.z, acc[1][2]); acc[1][3] = fmaf(x1, wa.w, acc[1][3]);
            acc[1][4] = fmaf(x1, wb.x, acc[1][4]); acc[1][5] = fmaf(x1, wb.y, acc[1][5]);
            acc[1][6] = fmaf(x1, wb.z, acc[1][6]); acc[1][7] = fmaf(x1, wb.w, acc[1][7]);
            acc[2][0] = fmaf(x2, wa.x, acc[2][0]); acc[2][1] = fmaf(x2, wa.y, acc[2][1]);
            acc[2][2] = fmaf(x2, wa.z, acc[2][2]); acc[2][3] = fmaf(x2, wa.w, acc[2][3]);
            acc[2][4] = fmaf(x2, wb.x, acc[2][4]); acc[2][5] = fmaf(x2, wb.y, acc[2][5]);
            acc[2][6] = fmaf(x2, wb.z, acc[2][6]); acc[2][7] = fmaf(x2, wb.w, acc[2][7]);
            acc[3][0] = fmaf(x3, wa.x, acc[3][0]); acc[3][1] = fmaf(x3, wa.y, acc[3][1]);
            acc[3][2] = fmaf(x3, wa.z, acc[3][2]); acc[3][3] = fmaf(x3, wa.w, acc[3][3]);
            acc[3][4] = fmaf(x3, wb.x, acc[3][4]); acc[3][5] = fmaf(x3, wb.y, acc[3][5]);
            acc[3][6] = fmaf(x3, wb.z, acc[3][6]); acc[3][7] = fmaf(x3, wb.w, acc[3][7]);
        }
        float* outp = (m==0) ? g_Q : (m==1) ? g_K : (m==2) ? g_V : g_G;
        if (m == 3) {
            float bgv[8];
            #pragma unroll
            for (int c = 0; c < 8; c++) bgv[c] = bg[tx*8 + c];
            #pragma unroll
            for (int j = 0; j < 4; j++) {
                float v[8];
                #pragma unroll
                for (int c = 0; c < 8; c++) v[c] = 1.f/(1.f + __expf(-(acc[j][c] + bgv[c])));
                size_t base = (size_t)(r0 + ty*4 + j)*DD + tx*8;
                *(float4*)(outp + base)     = make_float4(v[0], v[1], v[2], v[3]);
                *(float4*)(outp + base + 4) = make_float4(v[4], v[5], v[6], v[7]);
            }
        } else {
            #pragma unroll
            for (int j = 0; j < 4; j++) {
                size_t base = (size_t)(r0 + ty*4 + j)*DD + tx*8;
                *(float4*)(outp + base)     = make_float4(acc[j][0], acc[j][1], acc[j][2], acc[j][3]);
                *(float4*)(outp + base + 4) = make_float4(acc[j][4], acc[j][5], acc[j][6], acc[j][7]);
            }
        }
    }
}

// ---------------------------------------------------------------------------
// Kernel 2: attention per (i, h). 256 threads = 8 warps.
// QK: warp owns 8 queries, lane owns 10 keys (k = lane + 32j). Softmax in regs.
// Probabilities stored TRANSPOSED (PT[k][q], pitch 68) for float4 PV reads.
// PV: 2-way k-split; thread tile 4q x 4dh.
// ---------------------------------------------------------------------------
__global__ void __launch_bounds__(256) attn_kernel()
{
    extern __shared__ float sm[];
    float* Ks = sm;                    // 320*36 = 11520
    float* Vs = Ks + 11520;            // 320*36 = 11520
    float* Qs = Vs + 11520;            // 64*36 = 2304 (reused as PV partial buffer, pitch 33)
    float* PT = Qs + 2304;             // 320*68 = 21760
    float* bs = PT + 21760;            // 320

    const float4* Ks4 = (const float4*)Ks;
    const float4* Vs4 = (const float4*)Vs;
    const float4* Qs4 = (const float4*)Qs;
    const float4* PT4 = (const float4*)PT;

    int h = blockIdx.x, i = blockIdx.y;
    int tid = threadIdx.x;
    int warp = tid >> 5, lane = tid & 31;
    size_t rowbase = ((size_t)i * LL) * DD + h * DH;

    for (int idx = tid; idx < LL*DH; idx += 256) {
        int j = idx >> 5, d = idx & 31;
        Ks[j*36 + d] = g_K[rowbase + (size_t)j*DD + d];
        Vs[j*36 + d] = g_V[rowbase + (size_t)j*DD + d];
    }
    for (int idx = tid; idx < LL; idx += 256) bs[idx] = g_Bb[(i*NH + h)*LL + idx];
    __syncthreads();

    const float scale = 0.17677669529663687f;  // 1/sqrt(32)
    int qb = warp * 8;
    // PV mapping
    int half = tid >> 7, tl = tid & 127;
    int px = tl & 15, py = tl >> 4;            // px: q-group of 4, py: dh-group of 4

    #pragma unroll 1
    for (int t = 0; t < 5; t++) {
        // stage Q tile (64 x 32)
        for (int idx = tid; idx < 64*32; idx += 256) {
            int q = idx >> 5, d = idx & 31;
            Qs[q*36 + d] = g_Q[rowbase + (size_t)(t*64 + q)*DD + d];
        }
        __syncthreads();

        // ---- QK: acc[qi][j] = <Q[qb+qi], K[lane+32j]> ----
        float acc[8][10];
        #pragma unroll
        for (int qi = 0; qi < 8; qi++)
            #pragma unroll
            for (int j = 0; j < 10; j++) acc[qi][j] = 0.f;

        #pragma unroll 1
        for (int d4 = 0; d4 < 8; d4++) {
            #pragma unroll
            for (int jh = 0; jh < 2; jh++) {
                float4 kv[5];
                #pragma unroll
                for (int j = 0; j < 5; j++) kv[j] = Ks4[(lane + 32*(jh*5+j))*9 + d4];
                #pragma unroll
                for (int qi = 0; qi < 8; qi++) {
                    float4 qv = Qs4[(qb+qi)*9 + d4];
                    #pragma unroll
                    for (int j = 0; j < 5; j++) {
                        float a = acc[qi][jh*5+j];
                        a = fmaf(qv.x, kv[j].x, a);
                        a = fmaf(qv.y, kv[j].y, a);
                        a = fmaf(qv.z, kv[j].z, a);
                        a = fmaf(qv.w, kv[j].w, a);
                        acc[qi][jh*5+j] = a;
                    }
                }
            }
        }

        // ---- softmax per query (k split across 32 lanes x 10) ----
        float bsr[10];
        #pragma unroll
        for (int j = 0; j < 10; j++) bsr[j] = bs[lane + 32*j];
        #pragma unroll
        for (int qi = 0; qi < 8; qi++) {
            float mx = -1e30f;
            #pragma unroll
            for (int j = 0; j < 10; j++) {
                float s = acc[qi][j]*scale + bsr[j];
                acc[qi][j] = s;
                mx = fmaxf(mx, s);
            }
            #pragma unroll
            for (int o = 16; o; o >>= 1) mx = fmaxf(mx, __shfl_xor_sync(0xffffffffu, mx, o));
            float sum = 0.f;
            #pragma unroll
            for (int j = 0; j < 10; j++) {
                float e = __expf(acc[qi][j] - mx);
                acc[qi][j] = e;
                sum += e;
            }
            #pragma unroll
            for (int o = 16; o; o >>= 1) sum += __shfl_xor_sync(0xffffffffu, sum, o);
            float inv = 1.f / sum;
            #pragma unroll
            for (int j = 0; j < 10; j++)
                PT[(lane + 32*j)*68 + qb + qi] = acc[qi][j] * inv;
        }
        __syncthreads();

        // ---- PV: out[q0+qq][dh0+dd], q0 = px*4, dh0 = py*4; k in [half*160, +160) ----
        float4 o0 = make_float4(0,0,0,0), o1 = o0, o2 = o0, o3 = o0;
        int kbeg = half * 160;
        #pragma unroll 4
        for (int kk = 0; kk < 160; kk++) {
            int k = kbeg + kk;
            float4 p = PT4[k*17 + px];
            float4 v = Vs4[k*9 + py];
            o0.x = fmaf(p.x, v.x, o0.x); o0.y = fmaf(p.x, v.y, o0.y);
            o0.z = fmaf(p.x, v.z, o0.z); o0.w = fmaf(p.x, v.w, o0.w);
            o1.x = fmaf(p.y, v.x, o1.x); o1.y = fmaf(p.y, v.y, o1.y);
            o1.z = fmaf(p.y, v.z, o1.z); o1.w = fmaf(p.y, v.w, o1.w);
            o2.x = fmaf(p.z, v.x, o2.x); o2.y = fmaf(p.z, v.y, o2.y);
            o2.z = fmaf(p.z, v.z, o2.z); o2.w = fmaf(p.z, v.w, o2.w);
            o3.x = fmaf(p.w, v.x, o3.x); o3.y = fmaf(p.w, v.y, o3.y);
            o3.z = fmaf(p.w, v.z, o3.z); o3.w = fmaf(p.w, v.w, o3.w);
        }
        if (half == 1) {  // write partials to the Qs buffer (pitch 33)
            float* pb = Qs;
            pb[(px*4+0)*33 + py*4+0] = o0.x; pb[(px*4+0)*33 + py*4+1] = o0.y;
            pb[(px*4+0)*33 + py*4+2] = o0.z; pb[(px*4+0)*33 + py*4+3] = o0.w;
            pb[(px*4+1)*33 + py*4+0] = o1.x; pb[(px*4+1)*33 + py*4+1] = o1.y;
            pb[(px*4+1)*33 + py*4+2] = o1.z; pb[(px*4+1)*33 + py*4+3] = o1.w;
            pb[(px*4+2)*33 + py*4+0] = o2.x; pb[(px*4+2)*33 + py*4+1] = o2.y;
            pb[(px*4+2)*33 + py*4+2] = o2.z; pb[(px*4+2)*33 + py*4+3] = o2.w;
            pb[(px*4+3)*33 + py*4+0] = o3.x; pb[(px*4+3)*33 + py*4+1] = o3.y;
            pb[(px*4+3)*33 + py*4+2] = o3.z; pb[(px*4+3)*33 + py*4+3] = o3.w;
        }
        __syncthreads();
        if (half == 0) {
            const float* pb = Qs;
            float4 oo[4] = {o0, o1, o2, o3};
            #pragma unroll
            for (int qq = 0; qq < 4; qq++) {
                int q = px*4 + qq;
                float4 part = make_float4(pb[q*33 + py*4+0], pb[q*33 + py*4+1],
                                          pb[q*33 + py*4+2], pb[q*33 + py*4+3]);
                size_t gb = rowbase + (size_t)(t*64 + q)*DD + py*4;
                float4 gv = *(const float4*)(g_G + gb);
                float4 res;
                res.x = (oo[qq].x + part.x) * gv.x;
                res.y = (oo[qq].y + part.y) * gv.y;
                res.z = (oo[qq].z + part.z) * gv.z;
                res.w = (oo[qq].w + part.w) * gv.w;
                *(float4*)(g_A + gb) = res;
            }
        }
        __syncthreads();  // protect Qs/PT for next tile
    }
}

// ---------------------------------------------------------------------------
// Kernel 3: out = pair + att @ Wo^T + bo  (same microkernel as kernel 1)
// ---------------------------------------------------------------------------
__global__ void __launch_bounds__(256) oproj_kernel(
    const float* __restrict__ pair, const float* __restrict__ Wo,
    const float* __restrict__ bo, float* __restrict__ out)
{
    extern __shared__ float sm[];
    float* xs = sm;              // 64*128
    float* WT = sm + 8192;       // 128*132

    int tid = threadIdx.x;
    int r0  = blockIdx.x * 64;

    for (int idx = tid; idx < 64*32; idx += 256) {
        int rr = idx >> 5, dd = (idx & 31) * 4;
        *(float4*)(xs + rr*DD + dd) = *(const float4*)(g_A + (size_t)(r0+rr)*DD + dd);
    }
    for (int idx = tid; idx < DD*DD; idx += 256) {
        int j = idx >> 7, d = idx & 127;
        WT[d*132 + j] = Wo[idx];
    }
    __syncthreads();

    int tx = tid & 15, ty = tid >> 4;
    const float4* WT4 = (const float4*)WT;
    float acc[4][8];
    #pragma unroll
    for (int j = 0; j < 4; j++)
        #pragma unroll
        for (int c = 0; c < 8; c++) acc[j][c] = 0.f;
    const float* xr0 = xs + (ty*4+0)*DD;
    const float* xr1 = xs + (ty*4+1)*DD;
    const float* xr2 = xs + (ty*4+2)*DD;
    const float* xr3 = xs + (ty*4+3)*DD;
    #pragma unroll 4
    for (int d = 0; d < DD; d++) {
        float4 wa = WT4[d*33 + tx*2];
        float4 wb = WT4[d*33 + tx*2 + 1];
        float x0 = xr0[d], x1 = xr1[d], x2 = xr2[d], x3 = xr3[d];
        acc[0][0] = fmaf(x0, wa.x, acc[0][0]); acc[0][1] = fmaf(x0, wa.y, acc[0][1]);
        acc[0][2] = fmaf(x0, wa.z, acc[0][2]); acc[0][3] = fmaf(x0, wa.w, acc[0][3]);
        acc[0][4] = fmaf(x0, wb.x, acc[0][4]); acc[0][5] = fmaf(x0, wb.y, acc[0][5]);
        acc[0][6] = fmaf(x0, wb.z, acc[0][6]); acc[0][7] = fmaf(x0, wb.w, acc[0][7]);
        acc[1][0] = fmaf(x1, wa.x, acc[1][0]); acc[1][1] = fmaf(x1, wa.y, acc[1][1]);
        acc[1][2] = fmaf(x1, wa.z, acc[1][2]); acc[1][3] = fmaf(x1, wa.w, acc[1][3]);
        acc[1][4] = fmaf(x1, wb.x, acc[1][4]); acc[1][5] = fmaf(x1, wb.y, acc[1][5]);
        acc[1][6] = fmaf(x1, wb.z, acc[1][6]); acc[1][7] = fmaf(x1, wb.w, acc[1][7]);
        acc[2][0] = fmaf(x2, wa.x, acc[2][0]); acc[2][1] = fmaf(x2, wa.y, acc[2][1]);
        acc[2][2] = fmaf(x2, wa.z, acc[2][2]); acc[2][3] = fmaf(x2, wa.w, acc[2][3]);
        acc[2][4] = fmaf(x2, wb.x, acc[2][4]); acc[2][5] = fmaf(x2, wb.y, acc[2][5]);
        acc[2][6] = fmaf(x2, wb.z, acc[2][6]); acc[2][7] = fmaf(x2, wb.w, acc[2][7]);
        acc[3][0] = fmaf(x3, wa.x, acc[3][0]); acc[3][1] = fmaf(x3, wa.y, acc[3][1]);
        acc[3][2] = fmaf(x3, wa.z, acc[3][2]); acc[3][3] = fmaf(x3, wa.w, acc[3][3]);
        acc[3][4] = fmaf(x3, wb.x, acc[3][4]); acc[3][5] = fmaf(x3, wb.y, acc[3][5]);
        acc[3][6] = fmaf(x3, wb.z, acc[3][6]); acc[3][7] = fmaf(x3, wb.w, acc[3][7]);
    }
    float bov[8];
    #pragma unroll
    for (int c = 0; c < 8; c++) bov[c] = bo[tx*8 + c];
    #pragma unroll
    for (int j = 0; j < 4; j++) {
        size_t base = (size_t)(r0 + ty*4 + j)*DD + tx*8;
        float4 p0 = *(const float4*)(pair + base);
        float4 p1 = *(const float4*)(pair + base + 4);
        *(float4*)(out + base) = make_float4(
            p0.x + bov[0] + acc[j][0], p0.y + bov[1] + acc[j][1],
            p0.z + bov[2] + acc[j][2], p0.w + bov[3] + acc[j][3]);
        *(float4*)(out + base + 4) = make_float4(
            p1.x + bov[4] + acc[j][4], p1.y + bov[5] + acc[j][5],
            p1.z + bov[6] + acc[j][6], p1.w + bov[7] + acc[j][7]);
    }
}

// ---------------------------------------------------------------------------
extern "C" void kernel_launch(void* const* d_in, const int* in_sizes, int n_in,
                              void* d_out, int out_size)
{
    const float* pair = (const float*)d_in[0];
    const float* nw   = (const float*)d_in[1];
    const float* nb   = (const float*)d_in[2];
    const float* Wq   = (const float*)d_in[3];
    const float* Wk   = (const float*)d_in[4];
    const float* Wv   = (const float*)d_in[5];
    const float* Wg   = (const float*)d_in[6];
    const float* bg   = (const float*)d_in[7];
    const float* Wo   = (const float*)d_in[8];
    const float* bo   = (const float*)d_in[9];
    const float* Wb   = (const float*)d_in[10];
    float* out = (float*)d_out;

    size_t sm1 = (size_t)(8192 + 16896 + 512 + 128 + 128) * sizeof(float);  // 103.4 KB
    size_t sm2 = (size_t)(11520 + 11520 + 2304 + 21760 + 320) * sizeof(float); // 189.7 KB
    size_t sm3 = (size_t)(8192 + 16896) * sizeof(float);                    // 100.4 KB

    cudaFuncSetAttribute(ln_proj_kernel, cudaFuncAttributeMaxDynamicSharedMemorySize, (int)sm1);
    cudaFuncSetAttribute(attn_kernel,    cudaFuncAttributeMaxDynamicSharedMemorySize, (int)sm2);
    cudaFuncSetAttribute(oproj_kernel,   cudaFuncAttributeMaxDynamicSharedMemorySize, (int)sm3);

    ln_proj_kernel<<<NR/64, 256, sm1>>>(pair, nw, nb, Wq, Wk, Wv, Wg, bg, Wb);
    attn_kernel<<<dim3(NH, LL), 256, sm2>>>();
    oproj_kernel<<<NR/64, 256, sm3>>>(pair, Wo, bo, out);
}

// round 9
// speedup vs baseline: 1.8875x; 1.4117x over previous
#include <cuda_runtime.h>
#include <cuda_bf16.h>
#include <stdint.h>

#define LL 320
#define DD 128
#define NH 4
#define DH 32
#define NR (LL*LL)

// Scratch (static device globals; no runtime allocation allowed)
__device__ float g_Q[NR*DD];
__device__ float g_K[NR*DD];
__device__ float g_V[NR*DD];
__device__ float g_G[NR*DD];
__device__ float g_Bb[LL*NH*LL];   // bias[i][h][j]
__device__ float g_A[NR*DD];       // gated attention output (pre-Wo)

// ---------------------------------------------------------------------------
// Helpers: mma.sync bf16 + ldmatrix (baseline sm_103-safe PTX)
// ---------------------------------------------------------------------------
__device__ __forceinline__ uint32_t smem_u32(const void* p) {
    uint32_t a;
    asm("{ .reg .u64 t; cvta.to.shared.u64 t, %1; cvt.u32.u64 %0, t; }" : "=r"(a) : "l"(p));
    return a;
}
__device__ __forceinline__ void ldsm4(uint32_t* r, uint32_t addr) {
    asm volatile("ldmatrix.sync.aligned.m8n8.x4.shared.b16 {%0,%1,%2,%3}, [%4];"
                 : "=r"(r[0]), "=r"(r[1]), "=r"(r[2]), "=r"(r[3]) : "r"(addr));
}
__device__ __forceinline__ void mma16816(float* c,
    uint32_t a0, uint32_t a1, uint32_t a2, uint32_t a3, uint32_t b0, uint32_t b1) {
    asm volatile(
        "mma.sync.aligned.m16n8k16.row.col.f32.bf16.bf16.f32 "
        "{%0,%1,%2,%3}, {%4,%5,%6,%7}, {%8,%9}, {%0,%1,%2,%3};"
        : "+f"(c[0]), "+f"(c[1]), "+f"(c[2]), "+f"(c[3])
        : "r"(a0), "r"(a1), "r"(a2), "r"(a3), "r"(b0), "r"(b1));
}
// pack two floats' bf16-hi into u32, return residuals
__device__ __forceinline__ uint32_t pack_hi2(float a, float b, float& ra, float& rb) {
    __nv_bfloat16 ha = __float2bfloat16_rn(a), hb = __float2bfloat16_rn(b);
    ra = a - __bfloat162float(ha);
    rb = b - __bfloat162float(hb);
    return (uint32_t)__bfloat16_as_ushort(ha) | ((uint32_t)__bfloat16_as_ushort(hb) << 16);
}
__device__ __forceinline__ uint32_t pack_bf2(float a, float b) {
    return (uint32_t)__bfloat16_as_ushort(__float2bfloat16_rn(a))
         | ((uint32_t)__bfloat16_as_ushort(__float2bfloat16_rn(b)) << 16);
}

// bf16 smem tiles: 128 rows x 128 cols, pitch 136 bf16 (272 B; 16B-bank stride 17%8=1 -> LDSM conflict-free)
#define PITCHB 272              // row pitch in bytes
#define A_HI_OFF 0
#define A_LO_OFF 34816
#define W_HI_OFF 69632
#define W_LO_OFF 104448
#define MISC_OFF 139264

// ---------------------------------------------------------------------------
// Kernel 1 (HMMA): LayerNorm + {Q,K,V,G} projections + attention bias.
// 256 threads, 128 rows/CTA. Split-bf16: D = Ahi*Whi + Ahi*Wlo + Alo*Whi.
// ---------------------------------------------------------------------------
__global__ void __launch_bounds__(256) ln_proj_mma(
    const float* __restrict__ pair, const float* __restrict__ nw, const float* __restrict__ nb,
    const float* __restrict__ Wq, const float* __restrict__ Wk, const float* __restrict__ Wv,
    const float* __restrict__ Wg, const float* __restrict__ bg, const float* __restrict__ Wb)
{
    extern __shared__ char smem[];
    uint32_t sb = smem_u32(smem);
    float* Wbs = (float*)(smem + MISC_OFF);           // 512 floats
    float* nws = (float*)(smem + MISC_OFF + 2048);    // 128
    float* nbs = (float*)(smem + MISC_OFF + 2560);    // 128
    float* bgs = (float*)(smem + MISC_OFF + 3072);    // 128

    int tid = threadIdx.x, warp = tid >> 5, lane = tid & 31;
    int r0 = blockIdx.x * 128;

    for (int i = tid; i < 512; i += 256) Wbs[i] = Wb[i];
    if (tid < 128) { nws[tid] = nw[tid]; nbs[tid] = nb[tid]; bgs[tid] = bg[tid]; }
    __syncthreads();

    // Phase A: LN (warp per row, 16 rows/warp) -> split-bf16 A tiles; bias proj from RAW pair
    for (int it = 0; it < 16; it++) {
        int rr = it * 8 + warp;
        int r = r0 + rr;
        int d0 = lane * 4;
        float4 v = *(const float4*)(pair + (size_t)r * DD + d0);
        float s  = v.x + v.y + v.z + v.w;
        float ss = v.x*v.x + v.y*v.y + v.z*v.z + v.w*v.w;
        #pragma unroll
        for (int o = 16; o; o >>= 1) {
            s  += __shfl_xor_sync(0xffffffffu, s,  o);
            ss += __shfl_xor_sync(0xffffffffu, ss, o);
        }
        float mu   = s * (1.0f/128.0f);
        float var  = ss * (1.0f/128.0f) - mu*mu;
        float rstd = rsqrtf(var + 1e-5f);
        float x0 = (v.x-mu)*rstd*nws[d0+0] + nbs[d0+0];
        float x1 = (v.y-mu)*rstd*nws[d0+1] + nbs[d0+1];
        float x2 = (v.z-mu)*rstd*nws[d0+2] + nbs[d0+2];
        float x3 = (v.w-mu)*rstd*nws[d0+3] + nbs[d0+3];
        float e0, e1, e2, e3;
        uint2 hi, lo;
        hi.x = pack_hi2(x0, x1, e0, e1);
        hi.y = pack_hi2(x2, x3, e2, e3);
        lo.x = pack_bf2(e0, e1);
        lo.y = pack_bf2(e2, e3);
        *(uint2*)(smem + A_HI_OFF + rr*PITCHB + lane*8) = hi;
        *(uint2*)(smem + A_LO_OFF + rr*PITCHB + lane*8) = lo;
        // bias from RAW pair
        #pragma unroll
        for (int h = 0; h < NH; h++) {
            const float* wb = Wbs + h*128 + d0;
            float p = v.x*wb[0] + v.y*wb[1] + v.z*wb[2] + v.w*wb[3];
            #pragma unroll
            for (int o = 16; o; o >>= 1) p += __shfl_xor_sync(0xffffffffu, p, o);
            if (lane == 0) g_Bb[((r/LL)*NH + h)*LL + (r % LL)] = p;
        }
    }
    __syncthreads();

    // warp tile: wr in 0..3 -> 32 rows, wc in 0..1 -> 64 cols
    int wr = warp & 3, wc = warp >> 2;
    uint32_t aaddr_hi = sb + A_HI_OFF + (wr*32 + (lane & 15))*PITCHB + (lane >> 4)*16;
    uint32_t aaddr_lo = aaddr_hi + (A_LO_OFF - A_HI_OFF);
    uint32_t baddr_hi = sb + W_HI_OFF + (wc*64 + (lane & 15))*PITCHB + (lane >> 4)*16;
    uint32_t baddr_lo = baddr_hi + (W_LO_OFF - W_HI_OFF);

    const float* Ws[4] = {Wq, Wk, Wv, Wg};
    int r_lo = lane >> 2, cp = (lane & 3) * 2;

    #pragma unroll 1
    for (int m = 0; m < 4; m++) {
        // stage W[m] as split bf16 (rows = out col j, cols = d) — n-major = col-major B fragment
        const float4* W4 = (const float4*)Ws[m];
        for (int idx = tid; idx < 4096; idx += 256) {
            int c = idx >> 5, d0 = (idx & 31) * 4;
            float4 w = W4[idx];
            float e0, e1, e2, e3;
            uint2 hi, lo;
            hi.x = pack_hi2(w.x, w.y, e0, e1);
            hi.y = pack_hi2(w.z, w.w, e2, e3);
            lo.x = pack_bf2(e0, e1);
            lo.y = pack_bf2(e2, e3);
            *(uint2*)(smem + W_HI_OFF + c*PITCHB + d0*2) = hi;
            *(uint2*)(smem + W_LO_OFF + c*PITCHB + d0*2) = lo;
        }
        __syncthreads();

        float acc[2][8][4];
        #pragma unroll
        for (int mt = 0; mt < 2; mt++)
            #pragma unroll
            for (int nt = 0; nt < 8; nt++)
                #pragma unroll
                for (int e = 0; e < 4; e++) acc[mt][nt][e] = 0.f;

        #pragma unroll 1
        for (int sp = 0; sp < 3; sp++) {
            uint32_t aa = (sp < 2) ? aaddr_hi : aaddr_lo;
            uint32_t bb = (sp == 1) ? baddr_lo : baddr_hi;
            #pragma unroll
            for (int ks = 0; ks < 8; ks++) {
                uint32_t af0[4], af1[4];
                ldsm4(af0, aa + ks*32);
                ldsm4(af1, aa + 16*PITCHB + ks*32);
                #pragma unroll
                for (int ntp = 0; ntp < 4; ntp++) {
                    uint32_t bf[4];
                    ldsm4(bf, bb + ntp*16*PITCHB + ks*32);
                    mma16816(acc[0][ntp*2+0], af0[0], af0[1], af0[2], af0[3], bf[0], bf[2]);
                    mma16816(acc[0][ntp*2+1], af0[0], af0[1], af0[2], af0[3], bf[1], bf[3]);
                    mma16816(acc[1][ntp*2+0], af1[0], af1[1], af1[2], af1[3], bf[0], bf[2]);
                    mma16816(acc[1][ntp*2+1], af1[0], af1[1], af1[2], af1[3], bf[1], bf[3]);
                }
            }
        }

        // epilogue
        float* dst = (m == 0) ? g_Q : (m == 1) ? g_K : (m == 2) ? g_V : g_G;
        #pragma unroll
        for (int mt = 0; mt < 2; mt++) {
            int row = r0 + wr*32 + mt*16 + r_lo;
            #pragma unroll
            for (int nt = 0; nt < 8; nt++) {
                int col = wc*64 + nt*8 + cp;
                float v0 = acc[mt][nt][0], v1 = acc[mt][nt][1];
                float v2 = acc[mt][nt][2], v3 = acc[mt][nt][3];
                if (m == 3) {
                    v0 = 1.f/(1.f + __expf(-(v0 + bgs[col])));
                    v1 = 1.f/(1.f + __expf(-(v1 + bgs[col+1])));
                    v2 = 1.f/(1.f + __expf(-(v2 + bgs[col])));
                    v3 = 1.f/(1.f + __expf(-(v3 + bgs[col+1])));
                }
                *(float2*)(dst + (size_t)row*DD + col)     = make_float2(v0, v1);
                *(float2*)(dst + (size_t)(row+8)*DD + col) = make_float2(v2, v3);
            }
        }
        __syncthreads();   // W smem reusable
    }
}

// ---------------------------------------------------------------------------
// Kernel 2: attention per (i, h). 256 threads = 8 warps. (SIMT, unchanged)
// ---------------------------------------------------------------------------
__global__ void __launch_bounds__(256) attn_kernel()
{
    extern __shared__ float sm[];
    float* Ks = sm;                    // 320*36 = 11520
    float* Vs = Ks + 11520;            // 320*36 = 11520
    float* Qs = Vs + 11520;            // 64*36 = 2304 (reused as PV partial buffer, pitch 33)
    float* PT = Qs + 2304;             // 320*68 = 21760
    float* bs = PT + 21760;            // 320

    const float4* Ks4 = (const float4*)Ks;
    const float4* Vs4 = (const float4*)Vs;
    const float4* Qs4 = (const float4*)Qs;
    const float4* PT4 = (const float4*)PT;

    int h = blockIdx.x, i = blockIdx.y;
    int tid = threadIdx.x;
    int warp = tid >> 5, lane = tid & 31;
    size_t rowbase = ((size_t)i * LL) * DD + h * DH;

    for (int idx = tid; idx < LL*DH; idx += 256) {
        int j = idx >> 5, d = idx & 31;
        Ks[j*36 + d] = g_K[rowbase + (size_t)j*DD + d];
        Vs[j*36 + d] = g_V[rowbase + (size_t)j*DD + d];
    }
    for (int idx = tid; idx < LL; idx += 256) bs[idx] = g_Bb[(i*NH + h)*LL + idx];
    __syncthreads();

    const float scale = 0.17677669529663687f;  // 1/sqrt(32)
    int qb = warp * 8;
    int half = tid >> 7, tl = tid & 127;
    int px = tl & 15, py = tl >> 4;

    #pragma unroll 1
    for (int t = 0; t < 5; t++) {
        for (int idx = tid; idx < 64*32; idx += 256) {
            int q = idx >> 5, d = idx & 31;
            Qs[q*36 + d] = g_Q[rowbase + (size_t)(t*64 + q)*DD + d];
        }
        __syncthreads();

        float acc[8][10];
        #pragma unroll
        for (int qi = 0; qi < 8; qi++)
            #pragma unroll
            for (int j = 0; j < 10; j++) acc[qi][j] = 0.f;

        #pragma unroll 1
        for (int d4 = 0; d4 < 8; d4++) {
            #pragma unroll
            for (int jh = 0; jh < 2; jh++) {
                float4 kv[5];
                #pragma unroll
                for (int j = 0; j < 5; j++) kv[j] = Ks4[(lane + 32*(jh*5+j))*9 + d4];
                #pragma unroll
                for (int qi = 0; qi < 8; qi++) {
                    float4 qv = Qs4[(qb+qi)*9 + d4];
                    #pragma unroll
                    for (int j = 0; j < 5; j++) {
                        float a = acc[qi][jh*5+j];
                        a = fmaf(qv.x, kv[j].x, a);
                        a = fmaf(qv.y, kv[j].y, a);
                        a = fmaf(qv.z, kv[j].z, a);
                        a = fmaf(qv.w, kv[j].w, a);
                        acc[qi][jh*5+j] = a;
                    }
                }
            }
        }

        float bsr[10];
        #pragma unroll
        for (int j = 0; j < 10; j++) bsr[j] = bs[lane + 32*j];
        #pragma unroll
        for (int qi = 0; qi < 8; qi++) {
            float mx = -1e30f;
            #pragma unroll
            for (int j = 0; j < 10; j++) {
                float s = acc[qi][j]*scale + bsr[j];
                acc[qi][j] = s;
                mx = fmaxf(mx, s);
            }
            #pragma unroll
            for (int o = 16; o; o >>= 1) mx = fmaxf(mx, __shfl_xor_sync(0xffffffffu, mx, o));
            float sum = 0.f;
            #pragma unroll
            for (int j = 0; j < 10; j++) {
                float e = __expf(acc[qi][j] - mx);
                acc[qi][j] = e;
                sum += e;
            }
            #pragma unroll
            for (int o = 16; o; o >>= 1) sum += __shfl_xor_sync(0xffffffffu, sum, o);
            float inv = 1.f / sum;
            #pragma unroll
            for (int j = 0; j < 10; j++)
                PT[(lane + 32*j)*68 + qb + qi] = acc[qi][j] * inv;
        }
        __syncthreads();

        float4 o0 = make_float4(0,0,0,0), o1 = o0, o2 = o0, o3 = o0;
        int kbeg = half * 160;
        #pragma unroll 4
        for (int kk = 0; kk < 160; kk++) {
            int k = kbeg + kk;
            float4 p = PT4[k*17 + px];
            float4 v = Vs4[k*9 + py];
            o0.x = fmaf(p.x, v.x, o0.x); o0.y = fmaf(p.x, v.y, o0.y);
            o0.z = fmaf(p.x, v.z, o0.z); o0.w = fmaf(p.x, v.w, o0.w);
            o1.x = fmaf(p.y, v.x, o1.x); o1.y = fmaf(p.y, v.y, o1.y);
            o1.z = fmaf(p.y, v.z, o1.z); o1.w = fmaf(p.y, v.w, o1.w);
            o2.x = fmaf(p.z, v.x, o2.x); o2.y = fmaf(p.z, v.y, o2.y);
            o2.z = fmaf(p.z, v.z, o2.z); o2.w = fmaf(p.z, v.w, o2.w);
            o3.x = fmaf(p.w, v.x, o3.x); o3.y = fmaf(p.w, v.y, o3.y);
            o3.z = fmaf(p.w, v.z, o3.z); o3.w = fmaf(p.w, v.w, o3.w);
        }
        if (half == 1) {
            float* pb = Qs;
            pb[(px*4+0)*33 + py*4+0] = o0.x; pb[(px*4+0)*33 + py*4+1] = o0.y;
            pb[(px*4+0)*33 + py*4+2] = o0.z; pb[(px*4+0)*33 + py*4+3] = o0.w;
            pb[(px*4+1)*33 + py*4+0] = o1.x; pb[(px*4+1)*33 + py*4+1] = o1.y;
            pb[(px*4+1)*33 + py*4+2] = o1.z; pb[(px*4+1)*33 + py*4+3] = o1.w;
            pb[(px*4+2)*33 + py*4+0] = o2.x; pb[(px*4+2)*33 + py*4+1] = o2.y;
            pb[(px*4+2)*33 + py*4+2] = o2.z; pb[(px*4+2)*33 + py*4+3] = o2.w;
            pb[(px*4+3)*33 + py*4+0] = o3.x; pb[(px*4+3)*33 + py*4+1] = o3.y;
            pb[(px*4+3)*33 + py*4+2] = o3.z; pb[(px*4+3)*33 + py*4+3] = o3.w;
        }
        __syncthreads();
        if (half == 0) {
            const float* pb = Qs;
            float4 oo[4] = {o0, o1, o2, o3};
            #pragma unroll
            for (int qq = 0; qq < 4; qq++) {
                int q = px*4 + qq;
                float4 part = make_float4(pb[q*33 + py*4+0], pb[q*33 + py*4+1],
                                          pb[q*33 + py*4+2], pb[q*33 + py*4+3]);
                size_t gb = rowbase + (size_t)(t*64 + q)*DD + py*4;
                float4 gv = *(const float4*)(g_G + gb);
                float4 res;
                res.x = (oo[qq].x + part.x) * gv.x;
                res.y = (oo[qq].y + part.y) * gv.y;
                res.z = (oo[qq].z + part.z) * gv.z;
                res.w = (oo[qq].w + part.w) * gv.w;
                *(float4*)(g_A + gb) = res;
            }
        }
        __syncthreads();
    }
}

// ---------------------------------------------------------------------------
// Kernel 3 (HMMA): out = pair + g_A @ Wo^T + bo. 128 rows/CTA, split-bf16.
// ---------------------------------------------------------------------------
__global__ void __launch_bounds__(256) oproj_mma(
    const float* __restrict__ pair, const float* __restrict__ Wo,
    const float* __restrict__ bo, float* __restrict__ out)
{
    extern __shared__ char smem[];
    uint32_t sb = smem_u32(smem);
    float* bos = (float*)(smem + MISC_OFF);  // 128 floats

    int tid = threadIdx.x, warp = tid >> 5, lane = tid & 31;
    int r0 = blockIdx.x * 128;

    if (tid < 128) bos[tid] = bo[tid];

    // stage A (g_A rows) and Wo as split-bf16
    for (int idx = tid; idx < 4096; idx += 256) {
        int r = idx >> 5, d0 = (idx & 31) * 4;
        float4 a = *(const float4*)(g_A + (size_t)(r0 + r) * DD + d0);
        float e0, e1, e2, e3;
        uint2 hi, lo;
        hi.x = pack_hi2(a.x, a.y, e0, e1);
        hi.y = pack_hi2(a.z, a.w, e2, e3);
        lo.x = pack_bf2(e0, e1);
        lo.y = pack_bf2(e2, e3);
        *(uint2*)(smem + A_HI_OFF + r*PITCHB + d0*2) = hi;
        *(uint2*)(smem + A_LO_OFF + r*PITCHB + d0*2) = lo;
    }
    const float4* W4 = (const float4*)Wo;
    for (int idx = tid; idx < 4096; idx += 256) {
        int c = idx >> 5, d0 = (idx & 31) * 4;
        float4 w = W4[idx];
        float e0, e1, e2, e3;
        uint2 hi, lo;
        hi.x = pack_hi2(w.x, w.y, e0, e1);
        hi.y = pack_hi2(w.z, w.w, e2, e3);
        lo.x = pack_bf2(e0, e1);
        lo.y = pack_bf2(e2, e3);
        *(uint2*)(smem + W_HI_OFF + c*PITCHB + d0*2) = hi;
        *(uint2*)(smem + W_LO_OFF + c*PITCHB + d0*2) = lo;
    }
    __syncthreads();

    int wr = warp & 3, wc = warp >> 2;
    uint32_t aaddr_hi = sb + A_HI_OFF + (wr*32 + (lane & 15))*PITCHB + (lane >> 4)*16;
    uint32_t aaddr_lo = aaddr_hi + (A_LO_OFF - A_HI_OFF);
    uint32_t baddr_hi = sb + W_HI_OFF + (wc*64 + (lane & 15))*PITCHB + (lane >> 4)*16;
    uint32_t baddr_lo = baddr_hi + (W_LO_OFF - W_HI_OFF);

    float acc[2][8][4];
    #pragma unroll
    for (int mt = 0; mt < 2; mt++)
        #pragma unroll
        for (int nt = 0; nt < 8; nt++)
            #pragma unroll
            for (int e = 0; e < 4; e++) acc[mt][nt][e] = 0.f;

    #pragma unroll 1
    for (int sp = 0; sp < 3; sp++) {
        uint32_t aa = (sp < 2) ? aaddr_hi : aaddr_lo;
        uint32_t bb = (sp == 1) ? baddr_lo : baddr_hi;
        #pragma unroll
        for (int ks = 0; ks < 8; ks++) {
            uint32_t af0[4], af1[4];
            ldsm4(af0, aa + ks*32);
            ldsm4(af1, aa + 16*PITCHB + ks*32);
            #pragma unroll
            for (int ntp = 0; ntp < 4; ntp++) {
                uint32_t bf[4];
                ldsm4(bf, bb + ntp*16*PITCHB + ks*32);
                mma16816(acc[0][ntp*2+0], af0[0], af0[1], af0[2], af0[3], bf[0], bf[2]);
                mma16816(acc[0][ntp*2+1], af0[0], af0[1], af0[2], af0[3], bf[1], bf[3]);
                mma16816(acc[1][ntp*2+0], af1[0], af1[1], af1[2], af1[3], bf[0], bf[2]);
                mma16816(acc[1][ntp*2+1], af1[0], af1[1], af1[2], af1[3], bf[1], bf[3]);
            }
        }
    }

    int r_lo = lane >> 2, cp = (lane & 3) * 2;
    #pragma unroll
    for (int mt = 0; mt < 2; mt++) {
        int row = r0 + wr*32 + mt*16 + r_lo;
        #pragma unroll
        for (int nt = 0; nt < 8; nt++) {
            int col = wc*64 + nt*8 + cp;
            size_t g0 = (size_t)row*DD + col;
            size_t g1 = (size_t)(row+8)*DD + col;
            float2 p0 = *(const float2*)(pair + g0);
            float2 p1 = *(const float2*)(pair + g1);
            *(float2*)(out + g0) = make_float2(p0.x + bos[col]   + acc[mt][nt][0],
                                               p0.y + bos[col+1] + acc[mt][nt][1]);
            *(float2*)(out + g1) = make_float2(p1.x + bos[col]   + acc[mt][nt][2],
                                               p1.y + bos[col+1] + acc[mt][nt][3]);
        }
    }
}

// ---------------------------------------------------------------------------
extern "C" void kernel_launch(void* const* d_in, const int* in_sizes, int n_in,
                              void* d_out, int out_size)
{
    const float* pair = (const float*)d_in[0];
    const float* nw   = (const float*)d_in[1];
    const float* nb   = (const float*)d_in[2];
    const float* Wq   = (const float*)d_in[3];
    const float* Wk   = (const float*)d_in[4];
    const float* Wv   = (const float*)d_in[5];
    const float* Wg   = (const float*)d_in[6];
    const float* bg   = (const float*)d_in[7];
    const float* Wo   = (const float*)d_in[8];
    const float* bo   = (const float*)d_in[9];
    const float* Wb   = (const float*)d_in[10];
    float* out = (float*)d_out;

    size_t sm1 = MISC_OFF + 3584;                                            // ~139.5 KB
    size_t sm2 = (size_t)(11520 + 11520 + 2304 + 21760 + 320) * sizeof(float); // ~189.7 KB
    size_t sm3 = MISC_OFF + 512;                                             // ~136.5 KB

    cudaFuncSetAttribute(ln_proj_mma, cudaFuncAttributeMaxDynamicSharedMemorySize, (int)sm1);
    cudaFuncSetAttribute(attn_kernel, cudaFuncAttributeMaxDynamicSharedMemorySize, (int)sm2);
    cudaFuncSetAttribute(oproj_mma,   cudaFuncAttributeMaxDynamicSharedMemorySize, (int)sm3);

    ln_proj_mma<<<NR/128, 256, sm1>>>(pair, nw, nb, Wq, Wk, Wv, Wg, bg, Wb);
    attn_kernel<<<dim3(NH, LL), 256, sm2>>>();
    oproj_mma<<<NR/128, 256, sm3>>>(pair, Wo, bo, out);
}

// round 12
// speedup vs baseline: 2.6136x; 1.3847x over previous
#include <cuda_runtime.h>
#include <cuda_bf16.h>
#include <stdint.h>

#define LL 320
#define DD 128
#define NH 4
#define DH 32
#define NR (LL*LL)

// Scratch (static device globals; no runtime allocation allowed)
__device__ float g_Q[NR*DD];
__device__ float g_K[NR*DD];
__device__ float g_V[NR*DD];
__device__ float g_G[NR*DD];
__device__ float g_Bb[LL*NH*LL];   // bias[i][h][j]
__device__ float g_A[NR*DD];       // gated attention output (pre-Wo)

// ---------------------------------------------------------------------------
// Helpers: mma.sync bf16 + ldmatrix (baseline sm_103-safe PTX)
// ---------------------------------------------------------------------------
__device__ __forceinline__ uint32_t smem_u32(const void* p) {
    uint32_t a;
    asm("{ .reg .u64 t; cvta.to.shared.u64 t, %1; cvt.u32.u64 %0, t; }" : "=r"(a) : "l"(p));
    return a;
}
__device__ __forceinline__ void ldsm4(uint32_t* r, uint32_t addr) {
    asm volatile("ldmatrix.sync.aligned.m8n8.x4.shared.b16 {%0,%1,%2,%3}, [%4];"
                 : "=r"(r[0]), "=r"(r[1]), "=r"(r[2]), "=r"(r[3]) : "r"(addr));
}
__device__ __forceinline__ void mma16816(float* c,
    uint32_t a0, uint32_t a1, uint32_t a2, uint32_t a3, uint32_t b0, uint32_t b1) {
    asm volatile(
        "mma.sync.aligned.m16n8k16.row.col.f32.bf16.bf16.f32 "
        "{%0,%1,%2,%3}, {%4,%5,%6,%7}, {%8,%9}, {%0,%1,%2,%3};"
        : "+f"(c[0]), "+f"(c[1]), "+f"(c[2]), "+f"(c[3])
        : "r"(a0), "r"(a1), "r"(a2), "r"(a3), "r"(b0), "r"(b1));
}
// pack two floats' bf16-hi into u32, return residuals
__device__ __forceinline__ uint32_t pack_hi2(float a, float b, float& ra, float& rb) {
    __nv_bfloat16 ha = __float2bfloat16_rn(a), hb = __float2bfloat16_rn(b);
    ra = a - __bfloat162float(ha);
    rb = b - __bfloat162float(hb);
    return (uint32_t)__bfloat16_as_ushort(ha) | ((uint32_t)__bfloat16_as_ushort(hb) << 16);
}
__device__ __forceinline__ uint32_t pack_bf2(float a, float b) {
    return (uint32_t)__bfloat16_as_ushort(__float2bfloat16_rn(a))
         | ((uint32_t)__bfloat16_as_ushort(__float2bfloat16_rn(b)) << 16);
}

// bf16 smem tiles for projections: pitch 136 bf16 (272 B; stride 17 units, odd -> LDSM conflict-free)
#define PITCHB 272
#define A_HI_OFF 0
#define A_LO_OFF 34816
#define W_HI_OFF 69632
#define W_LO_OFF 104448
#define MISC_OFF 139264

// ---------------------------------------------------------------------------
// Kernel 1 (HMMA): LayerNorm + {Q,K,V,G} projections + attention bias.
// ---------------------------------------------------------------------------
__global__ void __launch_bounds__(256) ln_proj_mma(
    const float* __restrict__ pair, const float* __restrict__ nw, const float* __restrict__ nb,
    const float* __restrict__ Wq, const float* __restrict__ Wk, const float* __restrict__ Wv,
    const float* __restrict__ Wg, const float* __restrict__ bg, const float* __restrict__ Wb)
{
    extern __shared__ char smem[];
    uint32_t sb = smem_u32(smem);
    float* Wbs = (float*)(smem + MISC_OFF);
    float* nws = (float*)(smem + MISC_OFF + 2048);
    float* nbs = (float*)(smem + MISC_OFF + 2560);
    float* bgs = (float*)(smem + MISC_OFF + 3072);

    int tid = threadIdx.x, warp = tid >> 5, lane = tid & 31;
    int r0 = blockIdx.x * 128;

    for (int i = tid; i < 512; i += 256) Wbs[i] = Wb[i];
    if (tid < 128) { nws[tid] = nw[tid]; nbs[tid] = nb[tid]; bgs[tid] = bg[tid]; }
    __syncthreads();

    for (int it = 0; it < 16; it++) {
        int rr = it * 8 + warp;
        int r = r0 + rr;
        int d0 = lane * 4;
        float4 v = *(const float4*)(pair + (size_t)r * DD + d0);
        float s  = v.x + v.y + v.z + v.w;
        float ss = v.x*v.x + v.y*v.y + v.z*v.z + v.w*v.w;
        #pragma unroll
        for (int o = 16; o; o >>= 1) {
            s  += __shfl_xor_sync(0xffffffffu, s,  o);
            ss += __shfl_xor_sync(0xffffffffu, ss, o);
        }
        float mu   = s * (1.0f/128.0f);
        float var  = ss * (1.0f/128.0f) - mu*mu;
        float rstd = rsqrtf(var + 1e-5f);
        float x0 = (v.x-mu)*rstd*nws[d0+0] + nbs[d0+0];
        float x1 = (v.y-mu)*rstd*nws[d0+1] + nbs[d0+1];
        float x2 = (v.z-mu)*rstd*nws[d0+2] + nbs[d0+2];
        float x3 = (v.w-mu)*rstd*nws[d0+3] + nbs[d0+3];
        float e0, e1, e2, e3;
        uint2 hi, lo;
        hi.x = pack_hi2(x0, x1, e0, e1);
        hi.y = pack_hi2(x2, x3, e2, e3);
        lo.x = pack_bf2(e0, e1);
        lo.y = pack_bf2(e2, e3);
        *(uint2*)(smem + A_HI_OFF + rr*PITCHB + lane*8) = hi;
        *(uint2*)(smem + A_LO_OFF + rr*PITCHB + lane*8) = lo;
        #pragma unroll
        for (int h = 0; h < NH; h++) {
            const float* wb = Wbs + h*128 + d0;
            float p = v.x*wb[0] + v.y*wb[1] + v.z*wb[2] + v.w*wb[3];
            #pragma unroll
            for (int o = 16; o; o >>= 1) p += __shfl_xor_sync(0xffffffffu, p, o);
            if (lane == 0) g_Bb[((r/LL)*NH + h)*LL + (r % LL)] = p;
        }
    }
    __syncthreads();

    int wr = warp & 3, wc = warp >> 2;
    uint32_t aaddr_hi = sb + A_HI_OFF + (wr*32 + (lane & 15))*PITCHB + (lane >> 4)*16;
    uint32_t aaddr_lo = aaddr_hi + (A_LO_OFF - A_HI_OFF);
    uint32_t baddr_hi = sb + W_HI_OFF + (wc*64 + (lane & 15))*PITCHB + (lane >> 4)*16;
    uint32_t baddr_lo = baddr_hi + (W_LO_OFF - W_HI_OFF);

    const float* Ws[4] = {Wq, Wk, Wv, Wg};
    int r_lo = lane >> 2, cp = (lane & 3) * 2;

    #pragma unroll 1
    for (int m = 0; m < 4; m++) {
        const float4* W4 = (const float4*)Ws[m];
        for (int idx = tid; idx < 4096; idx += 256) {
            int c = idx >> 5, d0 = (idx & 31) * 4;
            float4 w = W4[idx];
            float e0, e1, e2, e3;
            uint2 hi, lo;
            hi.x = pack_hi2(w.x, w.y, e0, e1);
            hi.y = pack_hi2(w.z, w.w, e2, e3);
            lo.x = pack_bf2(e0, e1);
            lo.y = pack_bf2(e2, e3);
            *(uint2*)(smem + W_HI_OFF + c*PITCHB + d0*2) = hi;
            *(uint2*)(smem + W_LO_OFF + c*PITCHB + d0*2) = lo;
        }
        __syncthreads();

        float acc[2][8][4];
        #pragma unroll
        for (int mt = 0; mt < 2; mt++)
            #pragma unroll
            for (int nt = 0; nt < 8; nt++)
                #pragma unroll
                for (int e = 0; e < 4; e++) acc[mt][nt][e] = 0.f;

        #pragma unroll 1
        for (int sp = 0; sp < 3; sp++) {
            uint32_t aa = (sp < 2) ? aaddr_hi : aaddr_lo;
            uint32_t bb = (sp == 1) ? baddr_lo : baddr_hi;
            #pragma unroll
            for (int ks = 0; ks < 8; ks++) {
                uint32_t af0[4], af1[4];
                ldsm4(af0, aa + ks*32);
                ldsm4(af1, aa + 16*PITCHB + ks*32);
                #pragma unroll
                for (int ntp = 0; ntp < 4; ntp++) {
                    uint32_t bf[4];
                    ldsm4(bf, bb + ntp*16*PITCHB + ks*32);
                    mma16816(acc[0][ntp*2+0], af0[0], af0[1], af0[2], af0[3], bf[0], bf[2]);
                    mma16816(acc[0][ntp*2+1], af0[0], af0[1], af0[2], af0[3], bf[1], bf[3]);
                    mma16816(acc[1][ntp*2+0], af1[0], af1[1], af1[2], af1[3], bf[0], bf[2]);
                    mma16816(acc[1][ntp*2+1], af1[0], af1[1], af1[2], af1[3], bf[1], bf[3]);
                }
            }
        }

        float* dst = (m == 0) ? g_Q : (m == 1) ? g_K : (m == 2) ? g_V : g_G;
        #pragma unroll
        for (int mt = 0; mt < 2; mt++) {
            int row = r0 + wr*32 + mt*16 + r_lo;
            #pragma unroll
            for (int nt = 0; nt < 8; nt++) {
                int col = wc*64 + nt*8 + cp;
                float v0 = acc[mt][nt][0], v1 = acc[mt][nt][1];
                float v2 = acc[mt][nt][2], v3 = acc[mt][nt][3];
                if (m == 3) {
                    v0 = 1.f/(1.f + __expf(-(v0 + bgs[col])));
                    v1 = 1.f/(1.f + __expf(-(v1 + bgs[col+1])));
                    v2 = 1.f/(1.f + __expf(-(v2 + bgs[col])));
                    v3 = 1.f/(1.f + __expf(-(v3 + bgs[col+1])));
                }
                *(float2*)(dst + (size_t)row*DD + col)     = make_float2(v0, v1);
                *(float2*)(dst + (size_t)(row+8)*DD + col) = make_float2(v2, v3);
            }
        }
        __syncthreads();
    }
}

// ---------------------------------------------------------------------------
// Kernel 2 (HMMA): attention per (i, h). 256 threads = 8 warps.
// QK: split-bf16, warp m16q x n80k. Softmax in regs + smem cross-warp stats.
// PV computed as O^T = Vt @ P^T (all non-trans ldmatrix), k split across 2 warps.
// ---------------------------------------------------------------------------
// smem byte offsets for attn
#define AKHI 0
#define AKLO 25600
#define AVTHI 51200
#define AVTLO 72192
#define APHI 93184
#define APLO 114176
#define AQHI 135168
#define AQLO 137728
#define ABS 140288
#define AMXP 141568
#define ASMP 142080
#define AOS0 142592
#define AOS1 146944
#define ASMEM_TOTAL 151296

__global__ void __launch_bounds__(256) attn_mma()
{
    extern __shared__ char smem[];
    uint32_t sb = smem_u32(smem);
    int h = blockIdx.x, i = blockIdx.y;
    int tid = threadIdx.x, warp = tid >> 5, lane = tid & 31;
    size_t rowbase = ((size_t)i * LL) * DD + h * DH;

    float* bs  = (float*)(smem + ABS);
    float* mxp = (float*)(smem + AMXP);
    float* smp = (float*)(smem + ASMP);
    float* Os0 = (float*)(smem + AOS0);
    float* Os1 = (float*)(smem + AOS1);

    // K -> split bf16 (keys-major, pitch 40 bf16 = 80B)
    for (int idx = tid; idx < 320*8; idx += 256) {
        int j = idx >> 3, d0 = (idx & 7) * 4;
        float4 v = *(const float4*)(g_K + rowbase + (size_t)j*DD + d0);
        float e0, e1, e2, e3;
        uint2 hi, lo;
        hi.x = pack_hi2(v.x, v.y, e0, e1);
        hi.y = pack_hi2(v.z, v.w, e2, e3);
        lo.x = pack_bf2(e0, e1);
        lo.y = pack_bf2(e2, e3);
        *(uint2*)(smem + AKHI + j*80 + d0*2) = hi;
        *(uint2*)(smem + AKLO + j*80 + d0*2) = lo;
    }
    // V -> transposed split bf16 Vt[dh][key], pitch 328 bf16 = 656B.
    {
        int d0 = warp * 4;
        for (int jt = 0; jt < 10; jt++) {
            int j = jt*32 + lane;
            float4 v = *(const float4*)(g_V + rowbase + (size_t)j*DD + d0);
            float vv[4] = {v.x, v.y, v.z, v.w};
            #pragma unroll
            for (int e = 0; e < 4; e++) {
                __nv_bfloat16 hb = __float2bfloat16_rn(vv[e]);
                float rr = vv[e] - __bfloat162float(hb);
                *(__nv_bfloat16*)(smem + AVTHI + (d0+e)*656 + j*2) = hb;
                *(__nv_bfloat16*)(smem + AVTLO + (d0+e)*656 + j*2) = __float2bfloat16_rn(rr);
            }
        }
    }
    for (int idx = tid; idx < 320; idx += 256) bs[idx] = g_Bb[(i*NH + h)*LL + idx];
    __syncthreads();

    // QK warp mapping: mwarp (q 16-rows), kwarp (80 keys)
    int mwarp = warp >> 2, kwarp = warp & 3;
    uint32_t qaddr_hi = sb + AQHI + (mwarp*16 + (lane & 15))*80 + (lane >> 4)*16;
    uint32_t qaddr_lo = qaddr_hi + (AQLO - AQHI);
    uint32_t kaddr_hi = sb + AKHI + (kwarp*80 + (lane & 15))*80 + (lane >> 4)*16;
    uint32_t kaddr_lo = kaddr_hi + (AKLO - AKHI);
    // PV warp mapping: mdh (dh 16-rows), nq (q 16-cols), kh (key half)
    int kh = warp & 1, nq = (warp >> 1) & 1, mdh = warp >> 2;
    uint32_t vaddr_hi = sb + AVTHI + (mdh*16 + (lane & 15))*656 + (lane >> 4)*16 + kh*320;
    uint32_t vaddr_lo = vaddr_hi + (AVTLO - AVTHI);
    uint32_t paddr_hi = sb + APHI + (nq*16 + (lane & 15))*656 + (lane >> 4)*16 + kh*320;
    uint32_t paddr_lo = paddr_hi + (APLO - APHI);
    float* Osk = kh ? Os1 : Os0;

    const float scale = 0.17677669529663687f;  // 1/sqrt(32)
    int r_lo = lane >> 2, cp = (lane & 3) * 2;

    #pragma unroll 1
    for (int t = 0; t < 10; t++) {
        // stage Q tile 32x32 split
        {
            int q = tid >> 3, d0 = (tid & 7) * 4;
            float4 v = *(const float4*)(g_Q + rowbase + (size_t)(t*32 + q)*DD + d0);
            float e0, e1, e2, e3;
            uint2 hi, lo;
            hi.x = pack_hi2(v.x, v.y, e0, e1);
            hi.y = pack_hi2(v.z, v.w, e2, e3);
            lo.x = pack_bf2(e0, e1);
            lo.y = pack_bf2(e2, e3);
            *(uint2*)(smem + AQHI + q*80 + d0*2) = hi;
            *(uint2*)(smem + AQLO + q*80 + d0*2) = lo;
        }
        __syncthreads();

        // ---- S = Q K^T (m16 x n80 per warp, 3 split passes) ----
        float acc[10][4];
        #pragma unroll
        for (int g = 0; g < 10; g++)
            #pragma unroll
            for (int e = 0; e < 4; e++) acc[g][e] = 0.f;

        uint32_t afh[2][4], afl[2][4];
        ldsm4(afh[0], qaddr_hi);       ldsm4(afh[1], qaddr_hi + 32);
        ldsm4(afl[0], qaddr_lo);       ldsm4(afl[1], qaddr_lo + 32);

        #pragma unroll 1
        for (int sp = 0; sp < 3; sp++) {
            uint32_t ka = (sp == 1) ? kaddr_lo : kaddr_hi;
            #pragma unroll
            for (int ks = 0; ks < 2; ks++) {
                uint32_t* af = (sp < 2) ? afh[ks] : afl[ks];
                #pragma unroll
                for (int p = 0; p < 5; p++) {
                    uint32_t bf[4];
                    ldsm4(bf, ka + p*1280 + ks*32);
                    mma16816(acc[p*2+0], af[0], af[1], af[2], af[3], bf[0], bf[2]);
                    mma16816(acc[p*2+1], af[0], af[1], af[2], af[3], bf[1], bf[3]);
                }
            }
        }

        // ---- scale + bias, row max ----
        float mx0 = -1e30f, mx1 = -1e30f;
        #pragma unroll
        for (int g = 0; g < 10; g++) {
            int key = kwarp*80 + g*8 + cp;
            float2 bb = *(const float2*)(bs + key);
            acc[g][0] = fmaf(acc[g][0], scale, bb.x);
            acc[g][1] = fmaf(acc[g][1], scale, bb.y);
            acc[g][2] = fmaf(acc[g][2], scale, bb.x);
            acc[g][3] = fmaf(acc[g][3], scale, bb.y);
            mx0 = fmaxf(mx0, fmaxf(acc[g][0], acc[g][1]));
            mx1 = fmaxf(mx1, fmaxf(acc[g][2], acc[g][3]));
        }
        #pragma unroll
        for (int o = 1; o <= 2; o <<= 1) {
            mx0 = fmaxf(mx0, __shfl_xor_sync(0xffffffffu, mx0, o));
            mx1 = fmaxf(mx1, __shfl_xor_sync(0xffffffffu, mx1, o));
        }
        if ((lane & 3) == 0) {
            mxp[(mwarp*16 + r_lo)*4 + kwarp]     = mx0;
            mxp[(mwarp*16 + r_lo + 8)*4 + kwarp] = mx1;
        }
        __syncthreads();
        {
            float4 m4 = *(const float4*)(mxp + (mwarp*16 + r_lo)*4);
            mx0 = fmaxf(fmaxf(m4.x, m4.y), fmaxf(m4.z, m4.w));
            float4 m5 = *(const float4*)(mxp + (mwarp*16 + r_lo + 8)*4);
            mx1 = fmaxf(fmaxf(m5.x, m5.y), fmaxf(m5.z, m5.w));
        }
        float s0 = 0.f, s1 = 0.f;
        #pragma unroll
        for (int g = 0; g < 10; g++) {
            acc[g][0] = __expf(acc[g][0] - mx0);
            acc[g][1] = __expf(acc[g][1] - mx0);
            acc[g][2] = __expf(acc[g][2] - mx1);
            acc[g][3] = __expf(acc[g][3] - mx1);
            s0 += acc[g][0] + acc[g][1];
            s1 += acc[g][2] + acc[g][3];
        }
        #pragma unroll
        for (int o = 1; o <= 2; o <<= 1) {
            s0 += __shfl_xor_sync(0xffffffffu, s0, o);
            s1 += __shfl_xor_sync(0xffffffffu, s1, o);
        }
        if ((lane & 3) == 0) {
            smp[(mwarp*16 + r_lo)*4 + kwarp]     = s0;
            smp[(mwarp*16 + r_lo + 8)*4 + kwarp] = s1;
        }
        __syncthreads();
        float inv0, inv1;
        {
            float4 m4 = *(const float4*)(smp + (mwarp*16 + r_lo)*4);
            inv0 = 1.f / (m4.x + m4.y + m4.z + m4.w);
            float4 m5 = *(const float4*)(smp + (mwarp*16 + r_lo + 8)*4);
            inv1 = 1.f / (m5.x + m5.y + m5.z + m5.w);
        }
        // ---- P split store ----
        int row0 = mwarp*16 + r_lo, row1 = row0 + 8;
        #pragma unroll
        for (int g = 0; g < 10; g++) {
            int key = kwarp*80 + g*8 + cp;
            float e0, e1;
            uint32_t hh = pack_hi2(acc[g][0]*inv0, acc[g][1]*inv0, e0, e1);
            uint32_t ll = pack_bf2(e0, e1);
            *(uint32_t*)(smem + APHI + row0*656 + key*2) = hh;
            *(uint32_t*)(smem + APLO + row0*656 + key*2) = ll;
            hh = pack_hi2(acc[g][2]*inv1, acc[g][3]*inv1, e0, e1);
            ll = pack_bf2(e0, e1);
            *(uint32_t*)(smem + APHI + row1*656 + key*2) = hh;
            *(uint32_t*)(smem + APLO + row1*656 + key*2) = ll;
        }
        __syncthreads();

        // ---- O^T = Vt @ P^T (m16dh x n16q per warp, half keys, 3 passes) ----
        float acc2[2][4];
        #pragma unroll
        for (int j = 0; j < 2; j++)
            #pragma unroll
            for (int e = 0; e < 4; e++) acc2[j][e] = 0.f;

        #pragma unroll 1
        for (int pass = 0; pass < 3; pass++) {
            uint32_t va = (pass == 1) ? vaddr_lo : vaddr_hi;
            uint32_t pa = (pass == 2) ? paddr_lo : paddr_hi;
            #pragma unroll
            for (int ks = 0; ks < 10; ks++) {
                uint32_t af[4], bf[4];
                ldsm4(af, va + ks*32);
                ldsm4(bf, pa + ks*32);
                mma16816(acc2[0], af[0], af[1], af[2], af[3], bf[0], bf[2]);
                mma16816(acc2[1], af[0], af[1], af[2], af[3], bf[1], bf[3]);
            }
        }
        // stage O^T partials
        #pragma unroll
        for (int j = 0; j < 2; j++) {
            int qq = nq*16 + j*8 + cp;
            int dh = mdh*16 + r_lo;
            *(float2*)(Osk + dh*34 + qq)     = make_float2(acc2[j][0], acc2[j][1]);
            *(float2*)(Osk + (dh+8)*34 + qq) = make_float2(acc2[j][2], acc2[j][3]);
        }
        __syncthreads();

        // ---- combine halves, gate, write ----
        {
            int q = tid >> 3, d0 = (tid & 7) * 4;
            size_t gb = rowbase + (size_t)(t*32 + q)*DD + d0;
            float4 gv = *(const float4*)(g_G + gb);
            float4 res;
            res.x = (Os0[(d0+0)*34 + q] + Os1[(d0+0)*34 + q]) * gv.x;
            res.y = (Os0[(d0+1)*34 + q] + Os1[(d0+1)*34 + q]) * gv.y;
            res.z = (Os0[(d0+2)*34 + q] + Os1[(d0+2)*34 + q]) * gv.z;
            res.w = (Os0[(d0+3)*34 + q] + Os1[(d0+3)*34 + q]) * gv.w;
            *(float4*)(g_A + gb) = res;
        }
        __syncthreads();
    }
}

// ---------------------------------------------------------------------------
// Kernel 3 (HMMA): out = pair + g_A @ Wo^T + bo. 128 rows/CTA, split-bf16.
// ---------------------------------------------------------------------------
__global__ void __launch_bounds__(256) oproj_mma(
    const float* __restrict__ pair, const float* __restrict__ Wo,
    const float* __restrict__ bo, float* __restrict__ out)
{
    extern __shared__ char smem[];
    uint32_t sb = smem_u32(smem);
    float* bos = (float*)(smem + MISC_OFF);

    int tid = threadIdx.x, warp = tid >> 5, lane = tid & 31;
    int r0 = blockIdx.x * 128;

    if (tid < 128) bos[tid] = bo[tid];

    for (int idx = tid; idx < 4096; idx += 256) {
        int r = idx >> 5, d0 = (idx & 31) * 4;
        float4 a = *(const float4*)(g_A + (size_t)(r0 + r) * DD + d0);
        float e0, e1, e2, e3;
        uint2 hi, lo;
        hi.x = pack_hi2(a.x, a.y, e0, e1);
        hi.y = pack_hi2(a.z, a.w, e2, e3);
        lo.x = pack_bf2(e0, e1);
        lo.y = pack_bf2(e2, e3);
        *(uint2*)(smem + A_HI_OFF + r*PITCHB + d0*2) = hi;
        *(uint2*)(smem + A_LO_OFF + r*PITCHB + d0*2) = lo;
    }
    const float4* W4 = (const float4*)Wo;
    for (int idx = tid; idx < 4096; idx += 256) {
        int c = idx >> 5, d0 = (idx & 31) * 4;
        float4 w = W4[idx];
        float e0, e1, e2, e3;
        uint2 hi, lo;
        hi.x = pack_hi2(w.x, w.y, e0, e1);
        hi.y = pack_hi2(w.z, w.w, e2, e3);
        lo.x = pack_bf2(e0, e1);
        lo.y = pack_bf2(e2, e3);
        *(uint2*)(smem + W_HI_OFF + c*PITCHB + d0*2) = hi;
        *(uint2*)(smem + W_LO_OFF + c*PITCHB + d0*2) = lo;
    }
    __syncthreads();

    int wr = warp & 3, wc = warp >> 2;
    uint32_t aaddr_hi = sb + A_HI_OFF + (wr*32 + (lane & 15))*PITCHB + (lane >> 4)*16;
    uint32_t aaddr_lo = aaddr_hi + (A_LO_OFF - A_HI_OFF);
    uint32_t baddr_hi = sb + W_HI_OFF + (wc*64 + (lane & 15))*PITCHB + (lane >> 4)*16;
    uint32_t baddr_lo = baddr_hi + (W_LO_OFF - W_HI_OFF);

    float acc[2][8][4];
    #pragma unroll
    for (int mt = 0; mt < 2; mt++)
        #pragma unroll
        for (int nt = 0; nt < 8; nt++)
            #pragma unroll
            for (int e = 0; e < 4; e++) acc[mt][nt][e] = 0.f;

    #pragma unroll 1
    for (int sp = 0; sp < 3; sp++) {
        uint32_t aa = (sp < 2) ? aaddr_hi : aaddr_lo;
        uint32_t bb = (sp == 1) ? baddr_lo : baddr_hi;
        #pragma unroll
        for (int ks = 0; ks < 8; ks++) {
            uint32_t af0[4], af1[4];
            ldsm4(af0, aa + ks*32);
            ldsm4(af1, aa + 16*PITCHB + ks*32);
            #pragma unroll
            for (int ntp = 0; ntp < 4; ntp++) {
                uint32_t bf[4];
                ldsm4(bf, bb + ntp*16*PITCHB + ks*32);
                mma16816(acc[0][ntp*2+0], af0[0], af0[1], af0[2], af0[3], bf[0], bf[2]);
                mma16816(acc[0][ntp*2+1], af0[0], af0[1], af0[2], af0[3], bf[1], bf[3]);
                mma16816(acc[1][ntp*2+0], af1[0], af1[1], af1[2], af1[3], bf[0], bf[2]);
                mma16816(acc[1][ntp*2+1], af1[0], af1[1], af1[2], af1[3], bf[1], bf[3]);
            }
        }
    }

    int r_lo = lane >> 2, cp = (lane & 3) * 2;
    #pragma unroll
    for (int mt = 0; mt < 2; mt++) {
        int row = r0 + wr*32 + mt*16 + r_lo;
        #pragma unroll
        for (int nt = 0; nt < 8; nt++) {
            int col = wc*64 + nt*8 + cp;
            size_t g0 = (size_t)row*DD + col;
            size_t g1 = (size_t)(row+8)*DD + col;
            float2 p0 = *(const float2*)(pair + g0);
            float2 p1 = *(const float2*)(pair + g1);
            *(float2*)(out + g0) = make_float2(p0.x + bos[col]   + acc[mt][nt][0],
                                               p0.y + bos[col+1] + acc[mt][nt][1]);
            *(float2*)(out + g1) = make_float2(p1.x + bos[col]   + acc[mt][nt][2],
                                               p1.y + bos[col+1] + acc[mt][nt][3]);
        }
    }
}

// ---------------------------------------------------------------------------
extern "C" void kernel_launch(void* const* d_in, const int* in_sizes, int n_in,
                              void* d_out, int out_size)
{
    const float* pair = (const float*)d_in[0];
    const float* nw   = (const float*)d_in[1];
    const float* nb   = (const float*)d_in[2];
    const float* Wq   = (const float*)d_in[3];
    const float* Wk   = (const float*)d_in[4];
    const float* Wv   = (const float*)d_in[5];
    const float* Wg   = (const float*)d_in[6];
    const float* bg   = (const float*)d_in[7];
    const float* Wo   = (const float*)d_in[8];
    const float* bo   = (const float*)d_in[9];
    const float* Wb   = (const float*)d_in[10];
    float* out = (float*)d_out;

    size_t sm1 = MISC_OFF + 3584;     // ~139.5 KB
    size_t sm2 = ASMEM_TOTAL;         // ~147.8 KB
    size_t sm3 = MISC_OFF + 512;      // ~136.5 KB

    cudaFuncSetAttribute(ln_proj_mma, cudaFuncAttributeMaxDynamicSharedMemorySize, (int)sm1);
    cudaFuncSetAttribute(attn_mma,    cudaFuncAttributeMaxDynamicSharedMemorySize, (int)sm2);
    cudaFuncSetAttribute(oproj_mma,   cudaFuncAttributeMaxDynamicSharedMemorySize, (int)sm3);

    ln_proj_mma<<<NR/128, 256, sm1>>>(pair, nw, nb, Wq, Wk, Wv, Wg, bg, Wb);
    attn_mma<<<dim3(NH, LL), 256, sm2>>>();
    oproj_mma<<<NR/128, 256, sm3>>>(pair, Wo, bo, out);
}

// round 13
// speedup vs baseline: 4.1903x; 1.6033x over previous
#include <cuda_runtime.h>
#include <cuda_bf16.h>
#include <cuda_fp16.h>
#include <stdint.h>

#define LL 320
#define DD 128
#define NH 4
#define DH 32
#define NR (LL*LL)

// Scratch (static device globals; no runtime allocation allowed)
__device__ float g_Q[NR*DD];
__device__ float g_K[NR*DD];
__device__ float g_V[NR*DD];
__device__ float g_G[NR*DD];
__device__ float g_Bb[LL*NH*LL];   // bias[i][h][j]
__device__ float g_A[NR*DD];       // gated attention output (pre-Wo)

// ---------------------------------------------------------------------------
// Helpers: mma.sync + ldmatrix (baseline sm_103-safe PTX)
// ---------------------------------------------------------------------------
__device__ __forceinline__ uint32_t smem_u32(const void* p) {
    uint32_t a;
    asm("{ .reg .u64 t; cvta.to.shared.u64 t, %1; cvt.u32.u64 %0, t; }" : "=r"(a) : "l"(p));
    return a;
}
__device__ __forceinline__ void ldsm4(uint32_t* r, uint32_t addr) {
    asm volatile("ldmatrix.sync.aligned.m8n8.x4.shared.b16 {%0,%1,%2,%3}, [%4];"
                 : "=r"(r[0]), "=r"(r[1]), "=r"(r[2]), "=r"(r[3]) : "r"(addr));
}
__device__ __forceinline__ void mma16816(float* c,
    uint32_t a0, uint32_t a1, uint32_t a2, uint32_t a3, uint32_t b0, uint32_t b1) {
    asm volatile(
        "mma.sync.aligned.m16n8k16.row.col.f32.bf16.bf16.f32 "
        "{%0,%1,%2,%3}, {%4,%5,%6,%7}, {%8,%9}, {%0,%1,%2,%3};"
        : "+f"(c[0]), "+f"(c[1]), "+f"(c[2]), "+f"(c[3])
        : "r"(a0), "r"(a1), "r"(a2), "r"(a3), "r"(b0), "r"(b1));
}
__device__ __forceinline__ void mma16816h(float* c,
    uint32_t a0, uint32_t a1, uint32_t a2, uint32_t a3, uint32_t b0, uint32_t b1) {
    asm volatile(
        "mma.sync.aligned.m16n8k16.row.col.f32.f16.f16.f32 "
        "{%0,%1,%2,%3}, {%4,%5,%6,%7}, {%8,%9}, {%0,%1,%2,%3};"
        : "+f"(c[0]), "+f"(c[1]), "+f"(c[2]), "+f"(c[3])
        : "r"(a0), "r"(a1), "r"(a2), "r"(a3), "r"(b0), "r"(b1));
}
// pack two floats' bf16-hi into u32, return residuals
__device__ __forceinline__ uint32_t pack_hi2(float a, float b, float& ra, float& rb) {
    __nv_bfloat16 ha = __float2bfloat16_rn(a), hb = __float2bfloat16_rn(b);
    ra = a - __bfloat162float(ha);
    rb = b - __bfloat162float(hb);
    return (uint32_t)__bfloat16_as_ushort(ha) | ((uint32_t)__bfloat16_as_ushort(hb) << 16);
}
__device__ __forceinline__ uint32_t pack_bf2(float a, float b) {
    return (uint32_t)__bfloat16_as_ushort(__float2bfloat16_rn(a))
         | ((uint32_t)__bfloat16_as_ushort(__float2bfloat16_rn(b)) << 16);
}
__device__ __forceinline__ uint32_t pack_h2(float a, float b) {
    __half2 h = __floats2half2_rn(a, b);
    return *reinterpret_cast<uint32_t*>(&h);
}

// bf16 smem tiles for projections: pitch 136 bf16 (272 B; 17 x 16B, odd -> LDSM conflict-free)
#define PITCHB 272
#define A_HI_OFF 0
#define A_LO_OFF 34816
#define W_HI_OFF 69632          // 64 rows x 272 = 17408
#define W_LO_OFF 87040
#define MISC_OFF 104448

// ---------------------------------------------------------------------------
// Kernel 1 (HMMA): LayerNorm + {Q,K,V,G} projections + attention bias.
// W staged in two 64-col chunks -> smem 105.5 KB -> 2 CTAs/SM.
// ---------------------------------------------------------------------------
__global__ void __launch_bounds__(256) ln_proj_mma(
    const float* __restrict__ pair, const float* __restrict__ nw, const float* __restrict__ nb,
    const float* __restrict__ Wq, const float* __restrict__ Wk, const float* __restrict__ Wv,
    const float* __restrict__ Wg, const float* __restrict__ bg, const float* __restrict__ Wb)
{
    extern __shared__ char smem[];
    uint32_t sb = smem_u32(smem);
    float* Wbs = (float*)(smem + MISC_OFF);
    float* nws = (float*)(smem + MISC_OFF + 2048);
    float* nbs = (float*)(smem + MISC_OFF + 2560);
    float* bgs = (float*)(smem + MISC_OFF + 3072);

    int tid = threadIdx.x, warp = tid >> 5, lane = tid & 31;
    int r0 = blockIdx.x * 128;

    for (int i = tid; i < 512; i += 256) Wbs[i] = Wb[i];
    if (tid < 128) { nws[tid] = nw[tid]; nbs[tid] = nb[tid]; bgs[tid] = bg[tid]; }
    __syncthreads();

    // Phase A: LN (warp per row) -> split-bf16 A tiles; bias proj from RAW pair
    for (int it = 0; it < 16; it++) {
        int rr = it * 8 + warp;
        int r = r0 + rr;
        int d0 = lane * 4;
        float4 v = *(const float4*)(pair + (size_t)r * DD + d0);
        float s  = v.x + v.y + v.z + v.w;
        float ss = v.x*v.x + v.y*v.y + v.z*v.z + v.w*v.w;
        #pragma unroll
        for (int o = 16; o; o >>= 1) {
            s  += __shfl_xor_sync(0xffffffffu, s,  o);
            ss += __shfl_xor_sync(0xffffffffu, ss, o);
        }
        float mu   = s * (1.0f/128.0f);
        float var  = ss * (1.0f/128.0f) - mu*mu;
        float rstd = rsqrtf(var + 1e-5f);
        float x0 = (v.x-mu)*rstd*nws[d0+0] + nbs[d0+0];
        float x1 = (v.y-mu)*rstd*nws[d0+1] + nbs[d0+1];
        float x2 = (v.z-mu)*rstd*nws[d0+2] + nbs[d0+2];
        float x3 = (v.w-mu)*rstd*nws[d0+3] + nbs[d0+3];
        float e0, e1, e2, e3;
        uint2 hi, lo;
        hi.x = pack_hi2(x0, x1, e0, e1);
        hi.y = pack_hi2(x2, x3, e2, e3);
        lo.x = pack_bf2(e0, e1);
        lo.y = pack_bf2(e2, e3);
        *(uint2*)(smem + A_HI_OFF + rr*PITCHB + lane*8) = hi;
        *(uint2*)(smem + A_LO_OFF + rr*PITCHB + lane*8) = lo;
        #pragma unroll
        for (int h = 0; h < NH; h++) {
            const float* wb = Wbs + h*128 + d0;
            float p = v.x*wb[0] + v.y*wb[1] + v.z*wb[2] + v.w*wb[3];
            #pragma unroll
            for (int o = 16; o; o >>= 1) p += __shfl_xor_sync(0xffffffffu, p, o);
            if (lane == 0) g_Bb[((r/LL)*NH + h)*LL + (r % LL)] = p;
        }
    }
    __syncthreads();

    // warp tile: wr (32 rows), wc (32 cols of the 64-col chunk)
    int wr = warp & 3, wc = warp >> 2;
    uint32_t aaddr_hi = sb + A_HI_OFF + (wr*32 + (lane & 15))*PITCHB + (lane >> 4)*16;
    uint32_t aaddr_lo = aaddr_hi + (A_LO_OFF - A_HI_OFF);
    uint32_t baddr_hi = sb + W_HI_OFF + (wc*32 + (lane & 15))*PITCHB + (lane >> 4)*16;
    uint32_t baddr_lo = baddr_hi + (W_LO_OFF - W_HI_OFF);

    const float* Ws[4] = {Wq, Wk, Wv, Wg};
    int r_lo = lane >> 2, cp = (lane & 3) * 2;

    #pragma unroll 1
    for (int m = 0; m < 4; m++) {
        const float4* W4 = (const float4*)Ws[m];
        #pragma unroll 1
        for (int ch = 0; ch < 2; ch++) {
            int c0 = ch * 64;
            for (int idx = tid; idx < 2048; idx += 256) {
                int c = idx >> 5, dq = idx & 31, d0 = dq * 4;
                float4 w = W4[(c0 + c)*32 + dq];
                float e0, e1, e2, e3;
                uint2 hi, lo;
                hi.x = pack_hi2(w.x, w.y, e0, e1);
                hi.y = pack_hi2(w.z, w.w, e2, e3);
                lo.x = pack_bf2(e0, e1);
                lo.y = pack_bf2(e2, e3);
                *(uint2*)(smem + W_HI_OFF + c*PITCHB + d0*2) = hi;
                *(uint2*)(smem + W_LO_OFF + c*PITCHB + d0*2) = lo;
            }
            __syncthreads();

            float acc[2][4][4];
            #pragma unroll
            for (int mt = 0; mt < 2; mt++)
                #pragma unroll
                for (int nt = 0; nt < 4; nt++)
                    #pragma unroll
                    for (int e = 0; e < 4; e++) acc[mt][nt][e] = 0.f;

            #pragma unroll 1
            for (int sp = 0; sp < 3; sp++) {
                uint32_t aa = (sp < 2) ? aaddr_hi : aaddr_lo;
                uint32_t bb = (sp == 1) ? baddr_lo : baddr_hi;
                #pragma unroll
                for (int ks = 0; ks < 8; ks++) {
                    uint32_t af0[4], af1[4];
                    ldsm4(af0, aa + ks*32);
                    ldsm4(af1, aa + 16*PITCHB + ks*32);
                    #pragma unroll
                    for (int ntp = 0; ntp < 2; ntp++) {
                        uint32_t bf[4];
                        ldsm4(bf, bb + ntp*16*PITCHB + ks*32);
                        mma16816(acc[0][ntp*2+0], af0[0], af0[1], af0[2], af0[3], bf[0], bf[2]);
                        mma16816(acc[0][ntp*2+1], af0[0], af0[1], af0[2], af0[3], bf[1], bf[3]);
                        mma16816(acc[1][ntp*2+0], af1[0], af1[1], af1[2], af1[3], bf[0], bf[2]);
                        mma16816(acc[1][ntp*2+1], af1[0], af1[1], af1[2], af1[3], bf[1], bf[3]);
                    }
                }
            }

            float* dst = (m == 0) ? g_Q : (m == 1) ? g_K : (m == 2) ? g_V : g_G;
            #pragma unroll
            for (int mt = 0; mt < 2; mt++) {
                int row = r0 + wr*32 + mt*16 + r_lo;
                #pragma unroll
                for (int nt = 0; nt < 4; nt++) {
                    int col = c0 + wc*32 + nt*8 + cp;
                    float v0 = acc[mt][nt][0], v1 = acc[mt][nt][1];
                    float v2 = acc[mt][nt][2], v3 = acc[mt][nt][3];
                    if (m == 3) {
                        v0 = 1.f/(1.f + __expf(-(v0 + bgs[col])));
                        v1 = 1.f/(1.f + __expf(-(v1 + bgs[col+1])));
                        v2 = 1.f/(1.f + __expf(-(v2 + bgs[col])));
                        v3 = 1.f/(1.f + __expf(-(v3 + bgs[col+1])));
                    }
                    *(float2*)(dst + (size_t)row*DD + col)     = make_float2(v0, v1);
                    *(float2*)(dst + (size_t)(row+8)*DD + col) = make_float2(v2, v3);
                }
            }
            __syncthreads();
        }
    }
}

// ---------------------------------------------------------------------------
// Kernel 2 (HMMA): attention per (i, h). QK split-bf16; PV single-pass fp16.
// smem ~106.8 KB -> 2 CTAs/SM.
// ---------------------------------------------------------------------------
#define AKHI 0
#define AKLO 25600
#define AVT  51200          // fp16 Vt[dh][key], 32 x 656B
#define AP   72192          // fp16 P^T[q][key], 32 x 656B
#define AQHI 93184
#define AQLO 95744
#define ABS  98304
#define AMXP 99584
#define ASMP 100096
#define AOS0 100608
#define AOS1 104960
#define ASMEM_TOTAL 109312

__global__ void __launch_bounds__(256) attn_mma()
{
    extern __shared__ char smem[];
    uint32_t sb = smem_u32(smem);
    int h = blockIdx.x, i = blockIdx.y;
    int tid = threadIdx.x, warp = tid >> 5, lane = tid & 31;
    size_t rowbase = ((size_t)i * LL) * DD + h * DH;

    float* bs  = (float*)(smem + ABS);
    float* mxp = (float*)(smem + AMXP);
    float* smp = (float*)(smem + ASMP);
    float* Os0 = (float*)(smem + AOS0);
    float* Os1 = (float*)(smem + AOS1);

    // K -> split bf16 (keys-major, pitch 80B)
    for (int idx = tid; idx < 320*8; idx += 256) {
        int j = idx >> 3, d0 = (idx & 7) * 4;
        float4 v = *(const float4*)(g_K + rowbase + (size_t)j*DD + d0);
        float e0, e1, e2, e3;
        uint2 hi, lo;
        hi.x = pack_hi2(v.x, v.y, e0, e1);
        hi.y = pack_hi2(v.z, v.w, e2, e3);
        lo.x = pack_bf2(e0, e1);
        lo.y = pack_bf2(e2, e3);
        *(uint2*)(smem + AKHI + j*80 + d0*2) = hi;
        *(uint2*)(smem + AKLO + j*80 + d0*2) = lo;
    }
    // V -> transposed fp16 Vt[dh][key], pitch 656B
    {
        int d0 = warp * 4;
        for (int jt = 0; jt < 10; jt++) {
            int j = jt*32 + lane;
            float4 v = *(const float4*)(g_V + rowbase + (size_t)j*DD + d0);
            float vv[4] = {v.x, v.y, v.z, v.w};
            #pragma unroll
            for (int e = 0; e < 4; e++)
                *(__half*)(smem + AVT + (d0+e)*656 + j*2) = __float2half_rn(vv[e]);
        }
    }
    for (int idx = tid; idx < 320; idx += 256) bs[idx] = g_Bb[(i*NH + h)*LL + idx];
    __syncthreads();

    // QK warp mapping: mwarp (q 16-rows), kwarp (80 keys)
    int mwarp = warp >> 2, kwarp = warp & 3;
    uint32_t qaddr_hi = sb + AQHI + (mwarp*16 + (lane & 15))*80 + (lane >> 4)*16;
    uint32_t qaddr_lo = qaddr_hi + (AQLO - AQHI);
    uint32_t kaddr_hi = sb + AKHI + (kwarp*80 + (lane & 15))*80 + (lane >> 4)*16;
    uint32_t kaddr_lo = kaddr_hi + (AKLO - AKHI);
    // PV warp mapping: mdh (dh 16-rows), nq (q 16-cols), kh (key half)
    int kh = warp & 1, nq = (warp >> 1) & 1, mdh = warp >> 2;
    uint32_t vaddr = sb + AVT + (mdh*16 + (lane & 15))*656 + (lane >> 4)*16 + kh*320;
    uint32_t paddr = sb + AP  + (nq*16  + (lane & 15))*656 + (lane >> 4)*16 + kh*320;
    float* Osk = kh ? Os1 : Os0;

    const float scale = 0.17677669529663687f;  // 1/sqrt(32)
    int r_lo = lane >> 2, cp = (lane & 3) * 2;

    #pragma unroll 1
    for (int t = 0; t < 10; t++) {
        {   // stage Q tile 32x32 split
            int q = tid >> 3, d0 = (tid & 7) * 4;
            float4 v = *(const float4*)(g_Q + rowbase + (size_t)(t*32 + q)*DD + d0);
            float e0, e1, e2, e3;
            uint2 hi, lo;
            hi.x = pack_hi2(v.x, v.y, e0, e1);
            hi.y = pack_hi2(v.z, v.w, e2, e3);
            lo.x = pack_bf2(e0, e1);
            lo.y = pack_bf2(e2, e3);
            *(uint2*)(smem + AQHI + q*80 + d0*2) = hi;
            *(uint2*)(smem + AQLO + q*80 + d0*2) = lo;
        }
        __syncthreads();

        // ---- S = Q K^T (m16 x n80 per warp, 3 split passes) ----
        float acc[10][4];
        #pragma unroll
        for (int g = 0; g < 10; g++)
            #pragma unroll
            for (int e = 0; e < 4; e++) acc[g][e] = 0.f;

        uint32_t afh[2][4], afl[2][4];
        ldsm4(afh[0], qaddr_hi);       ldsm4(afh[1], qaddr_hi + 32);
        ldsm4(afl[0], qaddr_lo);       ldsm4(afl[1], qaddr_lo + 32);

        #pragma unroll 1
        for (int sp = 0; sp < 3; sp++) {
            uint32_t ka = (sp == 1) ? kaddr_lo : kaddr_hi;
            #pragma unroll
            for (int ks = 0; ks < 2; ks++) {
                uint32_t* af = (sp < 2) ? afh[ks] : afl[ks];
                #pragma unroll
                for (int p = 0; p < 5; p++) {
                    uint32_t bf[4];
                    ldsm4(bf, ka + p*1280 + ks*32);
                    mma16816(acc[p*2+0], af[0], af[1], af[2], af[3], bf[0], bf[2]);
                    mma16816(acc[p*2+1], af[0], af[1], af[2], af[3], bf[1], bf[3]);
                }
            }
        }

        // ---- scale + bias, softmax ----
        float mx0 = -1e30f, mx1 = -1e30f;
        #pragma unroll
        for (int g = 0; g < 10; g++) {
            int key = kwarp*80 + g*8 + cp;
            float2 bb = *(const float2*)(bs + key);
            acc[g][0] = fmaf(acc[g][0], scale, bb.x);
            acc[g][1] = fmaf(acc[g][1], scale, bb.y);
            acc[g][2] = fmaf(acc[g][2], scale, bb.x);
            acc[g][3] = fmaf(acc[g][3], scale, bb.y);
            mx0 = fmaxf(mx0, fmaxf(acc[g][0], acc[g][1]));
            mx1 = fmaxf(mx1, fmaxf(acc[g][2], acc[g][3]));
        }
        #pragma unroll
        for (int o = 1; o <= 2; o <<= 1) {
            mx0 = fmaxf(mx0, __shfl_xor_sync(0xffffffffu, mx0, o));
            mx1 = fmaxf(mx1, __shfl_xor_sync(0xffffffffu, mx1, o));
        }
        if ((lane & 3) == 0) {
            mxp[(mwarp*16 + r_lo)*4 + kwarp]     = mx0;
            mxp[(mwarp*16 + r_lo + 8)*4 + kwarp] = mx1;
        }
        __syncthreads();
        {
            float4 m4 = *(const float4*)(mxp + (mwarp*16 + r_lo)*4);
            mx0 = fmaxf(fmaxf(m4.x, m4.y), fmaxf(m4.z, m4.w));
            float4 m5 = *(const float4*)(mxp + (mwarp*16 + r_lo + 8)*4);
            mx1 = fmaxf(fmaxf(m5.x, m5.y), fmaxf(m5.z, m5.w));
        }
        float s0 = 0.f, s1 = 0.f;
        #pragma unroll
        for (int g = 0; g < 10; g++) {
            acc[g][0] = __expf(acc[g][0] - mx0);
            acc[g][1] = __expf(acc[g][1] - mx0);
            acc[g][2] = __expf(acc[g][2] - mx1);
            acc[g][3] = __expf(acc[g][3] - mx1);
            s0 += acc[g][0] + acc[g][1];
            s1 += acc[g][2] + acc[g][3];
        }
        #pragma unroll
        for (int o = 1; o <= 2; o <<= 1) {
            s0 += __shfl_xor_sync(0xffffffffu, s0, o);
            s1 += __shfl_xor_sync(0xffffffffu, s1, o);
        }
        if ((lane & 3) == 0) {
            smp[(mwarp*16 + r_lo)*4 + kwarp]     = s0;
            smp[(mwarp*16 + r_lo + 8)*4 + kwarp] = s1;
        }
        __syncthreads();
        float inv0, inv1;
        {
            float4 m4 = *(const float4*)(smp + (mwarp*16 + r_lo)*4);
            inv0 = 1.f / (m4.x + m4.y + m4.z + m4.w);
            float4 m5 = *(const float4*)(smp + (mwarp*16 + r_lo + 8)*4);
            inv1 = 1.f / (m5.x + m5.y + m5.z + m5.w);
        }
        // ---- P store (fp16) ----
        int row0 = mwarp*16 + r_lo, row1 = row0 + 8;
        #pragma unroll
        for (int g = 0; g < 10; g++) {
            int key = kwarp*80 + g*8 + cp;
            *(uint32_t*)(smem + AP + row0*656 + key*2) = pack_h2(acc[g][0]*inv0, acc[g][1]*inv0);
            *(uint32_t*)(smem + AP + row1*656 + key*2) = pack_h2(acc[g][2]*inv1, acc[g][3]*inv1);
        }
        __syncthreads();

        // ---- O^T = Vt @ P^T (m16dh x n16q per warp, half keys, fp16 single pass) ----
        float acc2[2][4];
        #pragma unroll
        for (int j = 0; j < 2; j++)
            #pragma unroll
            for (int e = 0; e < 4; e++) acc2[j][e] = 0.f;

        #pragma unroll
        for (int ks = 0; ks < 10; ks++) {
            uint32_t af[4], bf[4];
            ldsm4(af, vaddr + ks*32);
            ldsm4(bf, paddr + ks*32);
            mma16816h(acc2[0], af[0], af[1], af[2], af[3], bf[0], bf[2]);
            mma16816h(acc2[1], af[0], af[1], af[2], af[3], bf[1], bf[3]);
        }
        #pragma unroll
        for (int j = 0; j < 2; j++) {
            int qq = nq*16 + j*8 + cp;
            int dh = mdh*16 + r_lo;
            *(float2*)(Osk + dh*34 + qq)     = make_float2(acc2[j][0], acc2[j][1]);
            *(float2*)(Osk + (dh+8)*34 + qq) = make_float2(acc2[j][2], acc2[j][3]);
        }
        __syncthreads();

        // ---- combine halves, gate, write ----
        {
            int q = tid >> 3, d0 = (tid & 7) * 4;
            size_t gb = rowbase + (size_t)(t*32 + q)*DD + d0;
            float4 gv = *(const float4*)(g_G + gb);
            float4 res;
            res.x = (Os0[(d0+0)*34 + q] + Os1[(d0+0)*34 + q]) * gv.x;
            res.y = (Os0[(d0+1)*34 + q] + Os1[(d0+1)*34 + q]) * gv.y;
            res.z = (Os0[(d0+2)*34 + q] + Os1[(d0+2)*34 + q]) * gv.z;
            res.w = (Os0[(d0+3)*34 + q] + Os1[(d0+3)*34 + q]) * gv.w;
            *(float4*)(g_A + gb) = res;
        }
        __syncthreads();
    }
}

// ---------------------------------------------------------------------------
// Kernel 3 (HMMA): out = pair + g_A @ Wo^T + bo. Chunked W -> 2 CTAs/SM.
// ---------------------------------------------------------------------------
__global__ void __launch_bounds__(256) oproj_mma(
    const float* __restrict__ pair, const float* __restrict__ Wo,
    const float* __restrict__ bo, float* __restrict__ out)
{
    extern __shared__ char smem[];
    uint32_t sb = smem_u32(smem);
    float* bos = (float*)(smem + MISC_OFF);

    int tid = threadIdx.x, warp = tid >> 5, lane = tid & 31;
    int r0 = blockIdx.x * 128;

    if (tid < 128) bos[tid] = bo[tid];

    for (int idx = tid; idx < 4096; idx += 256) {
        int r = idx >> 5, d0 = (idx & 31) * 4;
        float4 a = *(const float4*)(g_A + (size_t)(r0 + r) * DD + d0);
        float e0, e1, e2, e3;
        uint2 hi, lo;
        hi.x = pack_hi2(a.x, a.y, e0, e1);
        hi.y = pack_hi2(a.z, a.w, e2, e3);
        lo.x = pack_bf2(e0, e1);
        lo.y = pack_bf2(e2, e3);
        *(uint2*)(smem + A_HI_OFF + r*PITCHB + d0*2) = hi;
        *(uint2*)(smem + A_LO_OFF + r*PITCHB + d0*2) = lo;
    }
    __syncthreads();

    int wr = warp & 3, wc = warp >> 2;
    uint32_t aaddr_hi = sb + A_HI_OFF + (wr*32 + (lane & 15))*PITCHB + (lane >> 4)*16;
    uint32_t aaddr_lo = aaddr_hi + (A_LO_OFF - A_HI_OFF);
    uint32_t baddr_hi = sb + W_HI_OFF + (wc*32 + (lane & 15))*PITCHB + (lane >> 4)*16;
    uint32_t baddr_lo = baddr_hi + (W_LO_OFF - W_HI_OFF);
    int r_lo = lane >> 2, cp = (lane & 3) * 2;

    const float4* W4 = (const float4*)Wo;
    #pragma unroll 1
    for (int ch = 0; ch < 2; ch++) {
        int c0 = ch * 64;
        for (int idx = tid; idx < 2048; idx += 256) {
            int c = idx >> 5, dq = idx & 31, d0 = dq * 4;
            float4 w = W4[(c0 + c)*32 + dq];
            float e0, e1, e2, e3;
            uint2 hi, lo;
            hi.x = pack_hi2(w.x, w.y, e0, e1);
            hi.y = pack_hi2(w.z, w.w, e2, e3);
            lo.x = pack_bf2(e0, e1);
            lo.y = pack_bf2(e2, e3);
            *(uint2*)(smem + W_HI_OFF + c*PITCHB + d0*2) = hi;
            *(uint2*)(smem + W_LO_OFF + c*PITCHB + d0*2) = lo;
        }
        __syncthreads();

        float acc[2][4][4];
        #pragma unroll
        for (int mt = 0; mt < 2; mt++)
            #pragma unroll
            for (int nt = 0; nt < 4; nt++)
                #pragma unroll
                for (int e = 0; e < 4; e++) acc[mt][nt][e] = 0.f;

        #pragma unroll 1
        for (int sp = 0; sp < 3; sp++) {
            uint32_t aa = (sp < 2) ? aaddr_hi : aaddr_lo;
            uint32_t bb = (sp == 1) ? baddr_lo : baddr_hi;
            #pragma unroll
            for (int ks = 0; ks < 8; ks++) {
                uint32_t af0[4], af1[4];
                ldsm4(af0, aa + ks*32);
                ldsm4(af1, aa + 16*PITCHB + ks*32);
                #pragma unroll
                for (int ntp = 0; ntp < 2; ntp++) {
                    uint32_t bf[4];
                    ldsm4(bf, bb + ntp*16*PITCHB + ks*32);
                    mma16816(acc[0][ntp*2+0], af0[0], af0[1], af0[2], af0[3], bf[0], bf[2]);
                    mma16816(acc[0][ntp*2+1], af0[0], af0[1], af0[2], af0[3], bf[1], bf[3]);
                    mma16816(acc[1][ntp*2+0], af1[0], af1[1], af1[2], af1[3], bf[0], bf[2]);
                    mma16816(acc[1][ntp*2+1], af1[0], af1[1], af1[2], af1[3], bf[1], bf[3]);
                }
            }
        }

        #pragma unroll
        for (int mt = 0; mt < 2; mt++) {
            int row = r0 + wr*32 + mt*16 + r_lo;
            #pragma unroll
            for (int nt = 0; nt < 4; nt++) {
                int col = c0 + wc*32 + nt*8 + cp;
                size_t g0 = (size_t)row*DD + col;
                size_t g1 = (size_t)(row+8)*DD + col;
                float2 p0 = *(const float2*)(pair + g0);
                float2 p1 = *(const float2*)(pair + g1);
                *(float2*)(out + g0) = make_float2(p0.x + bos[col]   + acc[mt][nt][0],
                                                   p0.y + bos[col+1] + acc[mt][nt][1]);
                *(float2*)(out + g1) = make_float2(p1.x + bos[col]   + acc[mt][nt][2],
                                                   p1.y + bos[col+1] + acc[mt][nt][3]);
            }
        }
        __syncthreads();
    }
}

// ---------------------------------------------------------------------------
extern "C" void kernel_launch(void* const* d_in, const int* in_sizes, int n_in,
                              void* d_out, int out_size)
{
    const float* pair = (const float*)d_in[0];
    const float* nw   = (const float*)d_in[1];
    const float* nb   = (const float*)d_in[2];
    const float* Wq   = (const float*)d_in[3];
    const float* Wk   = (const float*)d_in[4];
    const float* Wv   = (const float*)d_in[5];
    const float* Wg   = (const float*)d_in[6];
    const float* bg   = (const float*)d_in[7];
    const float* Wo   = (const float*)d_in[8];
    const float* bo   = (const float*)d_in[9];
    const float* Wb   = (const float*)d_in[10];
    float* out = (float*)d_out;

    size_t sm1 = MISC_OFF + 3584;     // 108032 B ~ 105.5 KB -> 2 CTAs/SM
    size_t sm2 = ASMEM_TOTAL;         // 109312 B ~ 106.8 KB -> 2 CTAs/SM
    size_t sm3 = MISC_OFF + 512;      // 104960 B ~ 102.5 KB -> 2 CTAs/SM

    cudaFuncSetAttribute(ln_proj_mma, cudaFuncAttributeMaxDynamicSharedMemorySize, (int)sm1);
    cudaFuncSetAttribute(attn_mma,    cudaFuncAttributeMaxDynamicSharedMemorySize, (int)sm2);
    cudaFuncSetAttribute(oproj_mma,   cudaFuncAttributeMaxDynamicSharedMemorySize, (int)sm3);

    ln_proj_mma<<<NR/128, 256, sm1>>>(pair, nw, nb, Wq, Wk, Wv, Wg, bg, Wb);
    attn_mma<<<dim3(NH, LL), 256, sm2>>>();
    oproj_mma<<<NR/128, 256, sm3>>>(pair, Wo, bo, out);
}

// round 14
// speedup vs baseline: 5.5829x; 1.3323x over previous
#include <cuda_runtime.h>
#include <cuda_bf16.h>
#include <cuda_fp16.h>
#include <stdint.h>

#define LL 320
#define DD 128
#define NH 4
#define DH 32
#define NR (LL*LL)

// Scratch (static device globals; no runtime allocation allowed)
__device__ float g_Q[NR*DD];
__device__ float g_K[NR*DD];
__device__ float g_V[NR*DD];
__device__ float g_G[NR*DD];
__device__ float g_Bb[LL*NH*LL];   // bias[i][h][j]
__device__ float g_A[NR*DD];       // gated attention output (pre-Wo)

// ---------------------------------------------------------------------------
// Helpers: mma.sync fp16 + ldmatrix (baseline sm_103-safe PTX)
// ---------------------------------------------------------------------------
__device__ __forceinline__ uint32_t smem_u32(const void* p) {
    uint32_t a;
    asm("{ .reg .u64 t; cvta.to.shared.u64 t, %1; cvt.u32.u64 %0, t; }" : "=r"(a) : "l"(p));
    return a;
}
__device__ __forceinline__ void ldsm4(uint32_t* r, uint32_t addr) {
    asm volatile("ldmatrix.sync.aligned.m8n8.x4.shared.b16 {%0,%1,%2,%3}, [%4];"
                 : "=r"(r[0]), "=r"(r[1]), "=r"(r[2]), "=r"(r[3]) : "r"(addr));
}
__device__ __forceinline__ void mma16816h(float* c,
    uint32_t a0, uint32_t a1, uint32_t a2, uint32_t a3, uint32_t b0, uint32_t b1) {
    asm volatile(
        "mma.sync.aligned.m16n8k16.row.col.f32.f16.f16.f32 "
        "{%0,%1,%2,%3}, {%4,%5,%6,%7}, {%8,%9}, {%0,%1,%2,%3};"
        : "+f"(c[0]), "+f"(c[1]), "+f"(c[2]), "+f"(c[3])
        : "r"(a0), "r"(a1), "r"(a2), "r"(a3), "r"(b0), "r"(b1));
}
__device__ __forceinline__ uint32_t pack_h2(float a, float b) {
    __half2 h = __floats2half2_rn(a, b);
    return *reinterpret_cast<uint32_t*>(&h);
}

// fp16 smem tiles: pitch 136 halves (272 B; 17 x 16B, odd -> LDSM conflict-free)
#define PITCHB 272
#define A_OFF 0
#define W_OFF 34816
#define MISC_OFF 69632

// ---------------------------------------------------------------------------
// Kernel 1 (HMMA fp16): LayerNorm + {Q,K,V,G} projections + attention bias.
// smem ~71.5 KB -> 3 CTAs/SM.
// ---------------------------------------------------------------------------
__global__ void __launch_bounds__(256) ln_proj_mma(
    const float* __restrict__ pair, const float* __restrict__ nw, const float* __restrict__ nb,
    const float* __restrict__ Wq, const float* __restrict__ Wk, const float* __restrict__ Wv,
    const float* __restrict__ Wg, const float* __restrict__ bg, const float* __restrict__ Wb)
{
    extern __shared__ char smem[];
    uint32_t sb = smem_u32(smem);
    float* Wbs = (float*)(smem + MISC_OFF);
    float* nws = (float*)(smem + MISC_OFF + 2048);
    float* nbs = (float*)(smem + MISC_OFF + 2560);
    float* bgs = (float*)(smem + MISC_OFF + 3072);

    int tid = threadIdx.x, warp = tid >> 5, lane = tid & 31;
    int r0 = blockIdx.x * 128;

    for (int i = tid; i < 512; i += 256) Wbs[i] = Wb[i];
    if (tid < 128) { nws[tid] = nw[tid]; nbs[tid] = nb[tid]; bgs[tid] = bg[tid]; }
    __syncthreads();

    // Phase A: LN (warp per row) -> fp16 A tile; bias proj from RAW pair
    for (int it = 0; it < 16; it++) {
        int rr = it * 8 + warp;
        int r = r0 + rr;
        int d0 = lane * 4;
        float4 v = *(const float4*)(pair + (size_t)r * DD + d0);
        float s  = v.x + v.y + v.z + v.w;
        float ss = v.x*v.x + v.y*v.y + v.z*v.z + v.w*v.w;
        #pragma unroll
        for (int o = 16; o; o >>= 1) {
            s  += __shfl_xor_sync(0xffffffffu, s,  o);
            ss += __shfl_xor_sync(0xffffffffu, ss, o);
        }
        float mu   = s * (1.0f/128.0f);
        float var  = ss * (1.0f/128.0f) - mu*mu;
        float rstd = rsqrtf(var + 1e-5f);
        float x0 = (v.x-mu)*rstd*nws[d0+0] + nbs[d0+0];
        float x1 = (v.y-mu)*rstd*nws[d0+1] + nbs[d0+1];
        float x2 = (v.z-mu)*rstd*nws[d0+2] + nbs[d0+2];
        float x3 = (v.w-mu)*rstd*nws[d0+3] + nbs[d0+3];
        uint2 hh;
        hh.x = pack_h2(x0, x1);
        hh.y = pack_h2(x2, x3);
        *(uint2*)(smem + A_OFF + rr*PITCHB + lane*8) = hh;
        #pragma unroll
        for (int h = 0; h < NH; h++) {
            const float* wb = Wbs + h*128 + d0;
            float p = v.x*wb[0] + v.y*wb[1] + v.z*wb[2] + v.w*wb[3];
            #pragma unroll
            for (int o = 16; o; o >>= 1) p += __shfl_xor_sync(0xffffffffu, p, o);
            if (lane == 0) g_Bb[((r/LL)*NH + h)*LL + (r % LL)] = p;
        }
    }
    __syncthreads();

    // warp tile: wr (32 rows), wc (64 cols)
    int wr = warp & 3, wc = warp >> 2;
    uint32_t aaddr = sb + A_OFF + (wr*32 + (lane & 15))*PITCHB + (lane >> 4)*16;
    uint32_t baddr = sb + W_OFF + (wc*64 + (lane & 15))*PITCHB + (lane >> 4)*16;

    const float* Ws[4] = {Wq, Wk, Wv, Wg};
    int r_lo = lane >> 2, cp = (lane & 3) * 2;

    #pragma unroll 1
    for (int m = 0; m < 4; m++) {
        const float4* W4 = (const float4*)Ws[m];
        for (int idx = tid; idx < 4096; idx += 256) {
            int c = idx >> 5, d0 = (idx & 31) * 4;
            float4 w = W4[idx];
            uint2 hh;
            hh.x = pack_h2(w.x, w.y);
            hh.y = pack_h2(w.z, w.w);
            *(uint2*)(smem + W_OFF + c*PITCHB + d0*2) = hh;
        }
        __syncthreads();

        float acc[2][8][4];
        #pragma unroll
        for (int mt = 0; mt < 2; mt++)
            #pragma unroll
            for (int nt = 0; nt < 8; nt++)
                #pragma unroll
                for (int e = 0; e < 4; e++) acc[mt][nt][e] = 0.f;

        #pragma unroll
        for (int ks = 0; ks < 8; ks++) {
            uint32_t af0[4], af1[4];
            ldsm4(af0, aaddr + ks*32);
            ldsm4(af1, aaddr + 16*PITCHB + ks*32);
            #pragma unroll
            for (int ntp = 0; ntp < 4; ntp++) {
                uint32_t bf[4];
                ldsm4(bf, baddr + ntp*16*PITCHB + ks*32);
                mma16816h(acc[0][ntp*2+0], af0[0], af0[1], af0[2], af0[3], bf[0], bf[2]);
                mma16816h(acc[0][ntp*2+1], af0[0], af0[1], af0[2], af0[3], bf[1], bf[3]);
                mma16816h(acc[1][ntp*2+0], af1[0], af1[1], af1[2], af1[3], bf[0], bf[2]);
                mma16816h(acc[1][ntp*2+1], af1[0], af1[1], af1[2], af1[3], bf[1], bf[3]);
            }
        }

        float* dst = (m == 0) ? g_Q : (m == 1) ? g_K : (m == 2) ? g_V : g_G;
        #pragma unroll
        for (int mt = 0; mt < 2; mt++) {
            int row = r0 + wr*32 + mt*16 + r_lo;
            #pragma unroll
            for (int nt = 0; nt < 8; nt++) {
                int col = wc*64 + nt*8 + cp;
                float v0 = acc[mt][nt][0], v1 = acc[mt][nt][1];
                float v2 = acc[mt][nt][2], v3 = acc[mt][nt][3];
                if (m == 3) {
                    v0 = 1.f/(1.f + __expf(-(v0 + bgs[col])));
                    v1 = 1.f/(1.f + __expf(-(v1 + bgs[col+1])));
                    v2 = 1.f/(1.f + __expf(-(v2 + bgs[col])));
                    v3 = 1.f/(1.f + __expf(-(v3 + bgs[col+1])));
                }
                *(float2*)(dst + (size_t)row*DD + col)     = make_float2(v0, v1);
                *(float2*)(dst + (size_t)(row+8)*DD + col) = make_float2(v2, v3);
            }
        }
        __syncthreads();
    }
}

// ---------------------------------------------------------------------------
// Kernel 2 (HMMA fp16): attention per (i, h). QK fp16 single-pass; PV fp16.
// smem ~79.3 KB -> 2 CTAs/SM.
// ---------------------------------------------------------------------------
#define AK   0              // fp16 K[key][d], pitch 80B, 320 rows = 25600
#define AVT  25600          // fp16 Vt[dh][key], 32 x 656B = 20992
#define AP   46592          // fp16 P^T[q][key], 32 x 656B = 20992
#define AQ   67584          // fp16 Q[q][d], 32 x 80B = 2560
#define ABS  70144          // 320 f32
#define AMXP 71424
#define ASMP 71936
#define AOS0 72448
#define AOS1 76800
#define ASMEM_TOTAL 81152

__global__ void __launch_bounds__(256) attn_mma()
{
    extern __shared__ char smem[];
    uint32_t sb = smem_u32(smem);
    int h = blockIdx.x, i = blockIdx.y;
    int tid = threadIdx.x, warp = tid >> 5, lane = tid & 31;
    size_t rowbase = ((size_t)i * LL) * DD + h * DH;

    float* bs  = (float*)(smem + ABS);
    float* mxp = (float*)(smem + AMXP);
    float* smp = (float*)(smem + ASMP);
    float* Os0 = (float*)(smem + AOS0);
    float* Os1 = (float*)(smem + AOS1);

    // K -> fp16 (keys-major, pitch 80B)
    for (int idx = tid; idx < 320*8; idx += 256) {
        int j = idx >> 3, d0 = (idx & 7) * 4;
        float4 v = *(const float4*)(g_K + rowbase + (size_t)j*DD + d0);
        uint2 hh;
        hh.x = pack_h2(v.x, v.y);
        hh.y = pack_h2(v.z, v.w);
        *(uint2*)(smem + AK + j*80 + d0*2) = hh;
    }
    // V -> transposed fp16 Vt[dh][key], pitch 656B
    {
        int d0 = warp * 4;
        for (int jt = 0; jt < 10; jt++) {
            int j = jt*32 + lane;
            float4 v = *(const float4*)(g_V + rowbase + (size_t)j*DD + d0);
            float vv[4] = {v.x, v.y, v.z, v.w};
            #pragma unroll
            for (int e = 0; e < 4; e++)
                *(__half*)(smem + AVT + (d0+e)*656 + j*2) = __float2half_rn(vv[e]);
        }
    }
    for (int idx = tid; idx < 320; idx += 256) bs[idx] = g_Bb[(i*NH + h)*LL + idx];
    __syncthreads();

    // QK warp mapping: mwarp (q 16-rows), kwarp (80 keys)
    int mwarp = warp >> 2, kwarp = warp & 3;
    uint32_t qaddr = sb + AQ + (mwarp*16 + (lane & 15))*80 + (lane >> 4)*16;
    uint32_t kaddr = sb + AK + (kwarp*80 + (lane & 15))*80 + (lane >> 4)*16;
    // PV warp mapping: mdh (dh 16-rows), nq (q 16-cols), kh (key half)
    int kh = warp & 1, nq = (warp >> 1) & 1, mdh = warp >> 2;
    uint32_t vaddr = sb + AVT + (mdh*16 + (lane & 15))*656 + (lane >> 4)*16 + kh*320;
    uint32_t paddr = sb + AP  + (nq*16  + (lane & 15))*656 + (lane >> 4)*16 + kh*320;
    float* Osk = kh ? Os1 : Os0;

    const float scale = 0.17677669529663687f;  // 1/sqrt(32)
    int r_lo = lane >> 2, cp = (lane & 3) * 2;

    #pragma unroll 1
    for (int t = 0; t < 10; t++) {
        {   // stage Q tile 32x32 fp16
            int q = tid >> 3, d0 = (tid & 7) * 4;
            float4 v = *(const float4*)(g_Q + rowbase + (size_t)(t*32 + q)*DD + d0);
            uint2 hh;
            hh.x = pack_h2(v.x, v.y);
            hh.y = pack_h2(v.z, v.w);
            *(uint2*)(smem + AQ + q*80 + d0*2) = hh;
        }
        __syncthreads();

        // ---- S = Q K^T (m16 x n80 per warp, single fp16 pass) ----
        float acc[10][4];
        #pragma unroll
        for (int g = 0; g < 10; g++)
            #pragma unroll
            for (int e = 0; e < 4; e++) acc[g][e] = 0.f;

        uint32_t af[2][4];
        ldsm4(af[0], qaddr);
        ldsm4(af[1], qaddr + 32);

        #pragma unroll
        for (int ks = 0; ks < 2; ks++) {
            #pragma unroll
            for (int p = 0; p < 5; p++) {
                uint32_t bf[4];
                ldsm4(bf, kaddr + p*1280 + ks*32);
                mma16816h(acc[p*2+0], af[ks][0], af[ks][1], af[ks][2], af[ks][3], bf[0], bf[2]);
                mma16816h(acc[p*2+1], af[ks][0], af[ks][1], af[ks][2], af[ks][3], bf[1], bf[3]);
            }
        }

        // ---- scale + bias, softmax ----
        float mx0 = -1e30f, mx1 = -1e30f;
        #pragma unroll
        for (int g = 0; g < 10; g++) {
            int key = kwarp*80 + g*8 + cp;
            float2 bb = *(const float2*)(bs + key);
            acc[g][0] = fmaf(acc[g][0], scale, bb.x);
            acc[g][1] = fmaf(acc[g][1], scale, bb.y);
            acc[g][2] = fmaf(acc[g][2], scale, bb.x);
            acc[g][3] = fmaf(acc[g][3], scale, bb.y);
            mx0 = fmaxf(mx0, fmaxf(acc[g][0], acc[g][1]));
            mx1 = fmaxf(mx1, fmaxf(acc[g][2], acc[g][3]));
        }
        #pragma unroll
        for (int o = 1; o <= 2; o <<= 1) {
            mx0 = fmaxf(mx0, __shfl_xor_sync(0xffffffffu, mx0, o));
            mx1 = fmaxf(mx1, __shfl_xor_sync(0xffffffffu, mx1, o));
        }
        if ((lane & 3) == 0) {
            mxp[(mwarp*16 + r_lo)*4 + kwarp]     = mx0;
            mxp[(mwarp*16 + r_lo + 8)*4 + kwarp] = mx1;
        }
        __syncthreads();
        {
            float4 m4 = *(const float4*)(mxp + (mwarp*16 + r_lo)*4);
            mx0 = fmaxf(fmaxf(m4.x, m4.y), fmaxf(m4.z, m4.w));
            float4 m5 = *(const float4*)(mxp + (mwarp*16 + r_lo + 8)*4);
            mx1 = fmaxf(fmaxf(m5.x, m5.y), fmaxf(m5.z, m5.w));
        }
        float s0 = 0.f, s1 = 0.f;
        #pragma unroll
        for (int g = 0; g < 10; g++) {
            acc[g][0] = __expf(acc[g][0] - mx0);
            acc[g][1] = __expf(acc[g][1] - mx0);
            acc[g][2] = __expf(acc[g][2] - mx1);
            acc[g][3] = __expf(acc[g][3] - mx1);
            s0 += acc[g][0] + acc[g][1];
            s1 += acc[g][2] + acc[g][3];
        }
        #pragma unroll
        for (int o = 1; o <= 2; o <<= 1) {
            s0 += __shfl_xor_sync(0xffffffffu, s0, o);
            s1 += __shfl_xor_sync(0xffffffffu, s1, o);
        }
        if ((lane & 3) == 0) {
            smp[(mwarp*16 + r_lo)*4 + kwarp]     = s0;
            smp[(mwarp*16 + r_lo + 8)*4 + kwarp] = s1;
        }
        __syncthreads();
        float inv0, inv1;
        {
            float4 m4 = *(const float4*)(smp + (mwarp*16 + r_lo)*4);
            inv0 = 1.f / (m4.x + m4.y + m4.z + m4.w);
            float4 m5 = *(const float4*)(smp + (mwarp*16 + r_lo + 8)*4);
            inv1 = 1.f / (m5.x + m5.y + m5.z + m5.w);
        }
        // ---- P store (fp16) ----
        int row0 = mwarp*16 + r_lo, row1 = row0 + 8;
        #pragma unroll
        for (int g = 0; g < 10; g++) {
            int key = kwarp*80 + g*8 + cp;
            *(uint32_t*)(smem + AP + row0*656 + key*2) = pack_h2(acc[g][0]*inv0, acc[g][1]*inv0);
            *(uint32_t*)(smem + AP + row1*656 + key*2) = pack_h2(acc[g][2]*inv1, acc[g][3]*inv1);
        }
        __syncthreads();

        // ---- O^T = Vt @ P^T (m16dh x n16q per warp, half keys) ----
        float acc2[2][4];
        #pragma unroll
        for (int j = 0; j < 2; j++)
            #pragma unroll
            for (int e = 0; e < 4; e++) acc2[j][e] = 0.f;

        #pragma unroll
        for (int ks = 0; ks < 10; ks++) {
            uint32_t vf[4], pf[4];
            ldsm4(vf, vaddr + ks*32);
            ldsm4(pf, paddr + ks*32);
            mma16816h(acc2[0], vf[0], vf[1], vf[2], vf[3], pf[0], pf[2]);
            mma16816h(acc2[1], vf[0], vf[1], vf[2], vf[3], pf[1], pf[3]);
        }
        #pragma unroll
        for (int j = 0; j < 2; j++) {
            int qq = nq*16 + j*8 + cp;
            int dh = mdh*16 + r_lo;
            *(float2*)(Osk + dh*34 + qq)     = make_float2(acc2[j][0], acc2[j][1]);
            *(float2*)(Osk + (dh+8)*34 + qq) = make_float2(acc2[j][2], acc2[j][3]);
        }
        __syncthreads();

        // ---- combine halves, gate, write ----
        {
            int q = tid >> 3, d0 = (tid & 7) * 4;
            size_t gb = rowbase + (size_t)(t*32 + q)*DD + d0;
            float4 gv = *(const float4*)(g_G + gb);
            float4 res;
            res.x = (Os0[(d0+0)*34 + q] + Os1[(d0+0)*34 + q]) * gv.x;
            res.y = (Os0[(d0+1)*34 + q] + Os1[(d0+1)*34 + q]) * gv.y;
            res.z = (Os0[(d0+2)*34 + q] + Os1[(d0+2)*34 + q]) * gv.z;
            res.w = (Os0[(d0+3)*34 + q] + Os1[(d0+3)*34 + q]) * gv.w;
            *(float4*)(g_A + gb) = res;
        }
        __syncthreads();
    }
}

// ---------------------------------------------------------------------------
// Kernel 3 (HMMA fp16): out = pair + g_A @ Wo^T + bo.
// ---------------------------------------------------------------------------
__global__ void __launch_bounds__(256) oproj_mma(
    const float* __restrict__ pair, const float* __restrict__ Wo,
    const float* __restrict__ bo, float* __restrict__ out)
{
    extern __shared__ char smem[];
    uint32_t sb = smem_u32(smem);
    float* bos = (float*)(smem + MISC_OFF);

    int tid = threadIdx.x, warp = tid >> 5, lane = tid & 31;
    int r0 = blockIdx.x * 128;

    if (tid < 128) bos[tid] = bo[tid];

    for (int idx = tid; idx < 4096; idx += 256) {
        int r = idx >> 5, d0 = (idx & 31) * 4;
        float4 a = *(const float4*)(g_A + (size_t)(r0 + r) * DD + d0);
        uint2 hh;
        hh.x = pack_h2(a.x, a.y);
        hh.y = pack_h2(a.z, a.w);
        *(uint2*)(smem + A_OFF + r*PITCHB + d0*2) = hh;
    }
    const float4* W4 = (const float4*)Wo;
    for (int idx = tid; idx < 4096; idx += 256) {
        int c = idx >> 5, d0 = (idx & 31) * 4;
        float4 w = W4[idx];
        uint2 hh;
        hh.x = pack_h2(w.x, w.y);
        hh.y = pack_h2(w.z, w.w);
        *(uint2*)(smem + W_OFF + c*PITCHB + d0*2) = hh;
    }
    __syncthreads();

    int wr = warp & 3, wc = warp >> 2;
    uint32_t aaddr = sb + A_OFF + (wr*32 + (lane & 15))*PITCHB + (lane >> 4)*16;
    uint32_t baddr = sb + W_OFF + (wc*64 + (lane & 15))*PITCHB + (lane >> 4)*16;

    float acc[2][8][4];
    #pragma unroll
    for (int mt = 0; mt < 2; mt++)
        #pragma unroll
        for (int nt = 0; nt < 8; nt++)
            #pragma unroll
            for (int e = 0; e < 4; e++) acc[mt][nt][e] = 0.f;

    #pragma unroll
    for (int ks = 0; ks < 8; ks++) {
        uint32_t af0[4], af1[4];
        ldsm4(af0, aaddr + ks*32);
        ldsm4(af1, aaddr + 16*PITCHB + ks*32);
        #pragma unroll
        for (int ntp = 0; ntp < 4; ntp++) {
            uint32_t bf[4];
            ldsm4(bf, baddr + ntp*16*PITCHB + ks*32);
            mma16816h(acc[0][ntp*2+0], af0[0], af0[1], af0[2], af0[3], bf[0], bf[2]);
            mma16816h(acc[0][ntp*2+1], af0[0], af0[1], af0[2], af0[3], bf[1], bf[3]);
            mma16816h(acc[1][ntp*2+0], af1[0], af1[1], af1[2], af1[3], bf[0], bf[2]);
            mma16816h(acc[1][ntp*2+1], af1[0], af1[1], af1[2], af1[3], bf[1], bf[3]);
        }
    }

    int r_lo = lane >> 2, cp = (lane & 3) * 2;
    #pragma unroll
    for (int mt = 0; mt < 2; mt++) {
        int row = r0 + wr*32 + mt*16 + r_lo;
        #pragma unroll
        for (int nt = 0; nt < 8; nt++) {
            int col = wc*64 + nt*8 + cp;
            size_t g0 = (size_t)row*DD + col;
            size_t g1 = (size_t)(row+8)*DD + col;
            float2 p0 = *(const float2*)(pair + g0);
            float2 p1 = *(const float2*)(pair + g1);
            *(float2*)(out + g0) = make_float2(p0.x + bos[col]   + acc[mt][nt][0],
                                               p0.y + bos[col+1] + acc[mt][nt][1]);
            *(float2*)(out + g1) = make_float2(p1.x + bos[col]   + acc[mt][nt][2],
                                               p1.y + bos[col+1] + acc[mt][nt][3]);
        }
    }
}

// ---------------------------------------------------------------------------
extern "C" void kernel_launch(void* const* d_in, const int* in_sizes, int n_in,
                              void* d_out, int out_size)
{
    const float* pair = (const float*)d_in[0];
    const float* nw   = (const float*)d_in[1];
    const float* nb   = (const float*)d_in[2];
    const float* Wq   = (const float*)d_in[3];
    const float* Wk   = (const float*)d_in[4];
    const float* Wv   = (const float*)d_in[5];
    const float* Wg   = (const float*)d_in[6];
    const float* bg   = (const float*)d_in[7];
    const float* Wo   = (const float*)d_in[8];
    const float* bo   = (const float*)d_in[9];
    const float* Wb   = (const float*)d_in[10];
    float* out = (float*)d_out;

    size_t sm1 = MISC_OFF + 3584;     // 73216 B ~ 71.5 KB -> 3 CTAs/SM
    size_t sm2 = ASMEM_TOTAL;         // 81152 B ~ 79.3 KB -> 2 CTAs/SM
    size_t sm3 = MISC_OFF + 512;      // 70144 B ~ 68.5 KB -> 3 CTAs/SM

    cudaFuncSetAttribute(ln_proj_mma, cudaFuncAttributeMaxDynamicSharedMemorySize, (int)sm1);
    cudaFuncSetAttribute(attn_mma,    cudaFuncAttributeMaxDynamicSharedMemorySize, (int)sm2);
    cudaFuncSetAttribute(oproj_mma,   cudaFuncAttributeMaxDynamicSharedMemorySize, (int)sm3);

    ln_proj_mma<<<NR/128, 256, sm1>>>(pair, nw, nb, Wq, Wk, Wv, Wg, bg, Wb);
    attn_mma<<<dim3(NH, LL), 256, sm2>>>();
    oproj_mma<<<NR/128, 256, sm3>>>(pair, Wo, bo, out);
}

// round 16
// speedup vs baseline: 7.1462x; 1.2800x over previous
#include <cuda_runtime.h>
#include <cuda_bf16.h>
#include <cuda_fp16.h>
#include <stdint.h>

#define LL 320
#define DD 128
#define NH 4
#define DH 32
#define NR (LL*LL)

// Scratch (static device globals; no runtime allocation allowed). fp16 intermediates.
__device__ __half g_Qh[NR*DD];
__device__ __half g_Kh[NR*DD];
__device__ __half g_Vh[NR*DD];
__device__ __half g_Gh[NR*DD];
__device__ __half g_Ah[NR*DD];
__device__ float  g_Bb[LL*NH*LL];   // bias[i][h][j] (fp32: feeds softmax logits)

// ---------------------------------------------------------------------------
// Helpers: mma.sync fp16 + ldmatrix (baseline sm_103-safe PTX)
// ---------------------------------------------------------------------------
__device__ __forceinline__ uint32_t smem_u32(const void* p) {
    uint32_t a;
    asm("{ .reg .u64 t; cvta.to.shared.u64 t, %1; cvt.u32.u64 %0, t; }" : "=r"(a) : "l"(p));
    return a;
}
__device__ __forceinline__ void ldsm4(uint32_t* r, uint32_t addr) {
    asm volatile("ldmatrix.sync.aligned.m8n8.x4.shared.b16 {%0,%1,%2,%3}, [%4];"
                 : "=r"(r[0]), "=r"(r[1]), "=r"(r[2]), "=r"(r[3]) : "r"(addr));
}
__device__ __forceinline__ void mma16816h(float* c,
    uint32_t a0, uint32_t a1, uint32_t a2, uint32_t a3, uint32_t b0, uint32_t b1) {
    asm volatile(
        "mma.sync.aligned.m16n8k16.row.col.f32.f16.f16.f32 "
        "{%0,%1,%2,%3}, {%4,%5,%6,%7}, {%8,%9}, {%0,%1,%2,%3};"
        : "+f"(c[0]), "+f"(c[1]), "+f"(c[2]), "+f"(c[3])
        : "r"(a0), "r"(a1), "r"(a2), "r"(a3), "r"(b0), "r"(b1));
}
__device__ __forceinline__ uint32_t pack_h2(float a, float b) {
    __half2 h = __floats2half2_rn(a, b);
    return *reinterpret_cast<uint32_t*>(&h);
}

// fp16 smem tiles: pitch 136 halves (272 B; 17 x 16B, odd -> LDSM conflict-free)
#define PITCHB 272
#define A_OFF 0                 // 128 x 272 = 34816
#define W_OFF 34816             // 64 x 272 = 17408 (chunked W)
#define MISC_OFF 52224

// ---------------------------------------------------------------------------
// Kernel 1 (HMMA fp16): LayerNorm + {Q,K,V,G} projections + attention bias.
// Chunked W (64 cols) -> acc 32 regs -> 3 CTAs/SM. fp16 outputs.
// ---------------------------------------------------------------------------
__global__ void __launch_bounds__(256, 3) ln_proj_mma(
    const float* __restrict__ pair, const float* __restrict__ nw, const float* __restrict__ nb,
    const float* __restrict__ Wq, const float* __restrict__ Wk, const float* __restrict__ Wv,
    const float* __restrict__ Wg, const float* __restrict__ bg, const float* __restrict__ Wb)
{
    extern __shared__ char smem[];
    uint32_t sb = smem_u32(smem);
    float* Wbs = (float*)(smem + MISC_OFF);
    float* nws = (float*)(smem + MISC_OFF + 2048);
    float* nbs = (float*)(smem + MISC_OFF + 2560);
    float* bgs = (float*)(smem + MISC_OFF + 3072);

    int tid = threadIdx.x, warp = tid >> 5, lane = tid & 31;
    int r0 = blockIdx.x * 128;

    for (int i = tid; i < 512; i += 256) Wbs[i] = Wb[i];
    if (tid < 128) { nws[tid] = nw[tid]; nbs[tid] = nb[tid]; bgs[tid] = bg[tid]; }
    __syncthreads();

    // Phase A: LN (warp per row) -> fp16 A tile; bias proj from RAW pair
    for (int it = 0; it < 16; it++) {
        int rr = it * 8 + warp;
        int r = r0 + rr;
        int d0 = lane * 4;
        float4 v = *(const float4*)(pair + (size_t)r * DD + d0);
        float s  = v.x + v.y + v.z + v.w;
        float ss = v.x*v.x + v.y*v.y + v.z*v.z + v.w*v.w;
        #pragma unroll
        for (int o = 16; o; o >>= 1) {
            s  += __shfl_xor_sync(0xffffffffu, s,  o);
            ss += __shfl_xor_sync(0xffffffffu, ss, o);
        }
        float mu   = s * (1.0f/128.0f);
        float var  = ss * (1.0f/128.0f) - mu*mu;
        float rstd = rsqrtf(var + 1e-5f);
        float x0 = (v.x-mu)*rstd*nws[d0+0] + nbs[d0+0];
        float x1 = (v.y-mu)*rstd*nws[d0+1] + nbs[d0+1];
        float x2 = (v.z-mu)*rstd*nws[d0+2] + nbs[d0+2];
        float x3 = (v.w-mu)*rstd*nws[d0+3] + nbs[d0+3];
        uint2 hh;
        hh.x = pack_h2(x0, x1);
        hh.y = pack_h2(x2, x3);
        *(uint2*)(smem + A_OFF + rr*PITCHB + lane*8) = hh;
        #pragma unroll
        for (int h = 0; h < NH; h++) {
            const float* wb = Wbs + h*128 + d0;
            float p = v.x*wb[0] + v.y*wb[1] + v.z*wb[2] + v.w*wb[3];
            #pragma unroll
            for (int o = 16; o; o >>= 1) p += __shfl_xor_sync(0xffffffffu, p, o);
            if (lane == 0) g_Bb[((r/LL)*NH + h)*LL + (r % LL)] = p;
        }
    }
    __syncthreads();

    // warp tile: wr (32 rows), wc (32 cols of the 64-col chunk)
    int wr = warp & 3, wc = warp >> 2;
    uint32_t aaddr = sb + A_OFF + (wr*32 + (lane & 15))*PITCHB + (lane >> 4)*16;
    uint32_t baddr = sb + W_OFF + (wc*32 + (lane & 15))*PITCHB + (lane >> 4)*16;

    const float* Ws[4] = {Wq, Wk, Wv, Wg};
    int r_lo = lane >> 2, cp = (lane & 3) * 2;

    #pragma unroll 1
    for (int m = 0; m < 4; m++) {
        const float4* W4 = (const float4*)Ws[m];
        #pragma unroll 1
        for (int ch = 0; ch < 2; ch++) {
            int c0 = ch * 64;
            for (int idx = tid; idx < 2048; idx += 256) {
                int c = idx >> 5, dq = idx & 31, d0 = dq * 4;
                float4 w = W4[(c0 + c)*32 + dq];
                uint2 hh;
                hh.x = pack_h2(w.x, w.y);
                hh.y = pack_h2(w.z, w.w);
                *(uint2*)(smem + W_OFF + c*PITCHB + d0*2) = hh;
            }
            __syncthreads();

            float acc[2][4][4];
            #pragma unroll
            for (int mt = 0; mt < 2; mt++)
                #pragma unroll
                for (int nt = 0; nt < 4; nt++)
                    #pragma unroll
                    for (int e = 0; e < 4; e++) acc[mt][nt][e] = 0.f;

            #pragma unroll
            for (int ks = 0; ks < 8; ks++) {
                uint32_t af0[4], af1[4];
                ldsm4(af0, aaddr + ks*32);
                ldsm4(af1, aaddr + 16*PITCHB + ks*32);
                #pragma unroll
                for (int ntp = 0; ntp < 2; ntp++) {
                    uint32_t bf[4];
                    ldsm4(bf, baddr + ntp*16*PITCHB + ks*32);
                    mma16816h(acc[0][ntp*2+0], af0[0], af0[1], af0[2], af0[3], bf[0], bf[2]);
                    mma16816h(acc[0][ntp*2+1], af0[0], af0[1], af0[2], af0[3], bf[1], bf[3]);
                    mma16816h(acc[1][ntp*2+0], af1[0], af1[1], af1[2], af1[3], bf[0], bf[2]);
                    mma16816h(acc[1][ntp*2+1], af1[0], af1[1], af1[2], af1[3], bf[1], bf[3]);
                }
            }

            __half* dst = (m == 0) ? g_Qh : (m == 1) ? g_Kh : (m == 2) ? g_Vh : g_Gh;
            #pragma unroll
            for (int mt = 0; mt < 2; mt++) {
                int row = r0 + wr*32 + mt*16 + r_lo;
                #pragma unroll
                for (int nt = 0; nt < 4; nt++) {
                    int col = c0 + wc*32 + nt*8 + cp;
                    float v0 = acc[mt][nt][0], v1 = acc[mt][nt][1];
                    float v2 = acc[mt][nt][2], v3 = acc[mt][nt][3];
                    if (m == 3) {
                        v0 = 1.f/(1.f + __expf(-(v0 + bgs[col])));
                        v1 = 1.f/(1.f + __expf(-(v1 + bgs[col+1])));
                        v2 = 1.f/(1.f + __expf(-(v2 + bgs[col])));
                        v3 = 1.f/(1.f + __expf(-(v3 + bgs[col+1])));
                    }
                    *(uint32_t*)(dst + (size_t)row*DD + col)     = pack_h2(v0, v1);
                    *(uint32_t*)(dst + (size_t)(row+8)*DD + col) = pack_h2(v2, v3);
                }
            }
            __syncthreads();
        }
    }
}

// ---------------------------------------------------------------------------
// Kernel 2 (HMMA fp16): attention per (i, h). All staging is plain fp16 copies.
// smem ~79.3 KB -> 2 CTAs/SM.
// ---------------------------------------------------------------------------
#define AK   0              // fp16 K[key][d], pitch 80B, 320 rows = 25600
#define AVT  25600          // fp16 Vt[dh][key], 32 x 656B = 20992
#define AP   46592          // fp16 P^T[q][key], 32 x 656B = 20992
#define AQ   67584          // fp16 Q[q][d], 32 x 80B = 2560
#define ABS  70144          // 320 f32
#define AMXP 71424
#define ASMP 71936
#define AOS0 72448
#define AOS1 76800
#define ASMEM_TOTAL 81152

__global__ void __launch_bounds__(256) attn_mma()
{
    extern __shared__ char smem[];
    uint32_t sb = smem_u32(smem);
    int h = blockIdx.x, i = blockIdx.y;
    int tid = threadIdx.x, warp = tid >> 5, lane = tid & 31;
    size_t rowbase = ((size_t)i * LL) * DD + h * DH;

    float* bs  = (float*)(smem + ABS);
    float* mxp = (float*)(smem + AMXP);
    float* smp = (float*)(smem + ASMP);
    float* Os0 = (float*)(smem + AOS0);
    float* Os1 = (float*)(smem + AOS1);

    // K: plain fp16 copy (keys-major, pitch 80B); 8 halves per thread-iter
    for (int idx = tid; idx < 320*4; idx += 256) {
        int j = idx >> 2, d0 = (idx & 3) * 8;
        *(uint4*)(smem + AK + j*80 + d0*2) = *(const uint4*)(g_Kh + rowbase + (size_t)j*DD + d0);
    }
    // V -> transposed fp16 Vt[dh][key], pitch 656B
    {
        int d0 = warp * 4;
        for (int jt = 0; jt < 10; jt++) {
            int j = jt*32 + lane;
            uint2 hv = *(const uint2*)(g_Vh + rowbase + (size_t)j*DD + d0);
            __half2 p01 = *(__half2*)&hv.x;
            __half2 p23 = *(__half2*)&hv.y;
            *(__half*)(smem + AVT + (d0+0)*656 + j*2) = __low2half(p01);
            *(__half*)(smem + AVT + (d0+1)*656 + j*2) = __high2half(p01);
            *(__half*)(smem + AVT + (d0+2)*656 + j*2) = __low2half(p23);
            *(__half*)(smem + AVT + (d0+3)*656 + j*2) = __high2half(p23);
        }
    }
    for (int idx = tid; idx < 320; idx += 256) bs[idx] = g_Bb[(i*NH + h)*LL + idx];
    __syncthreads();

    // QK warp mapping: mwarp (q 16-rows), kwarp (80 keys)
    int mwarp = warp >> 2, kwarp = warp & 3;
    uint32_t qaddr = sb + AQ + (mwarp*16 + (lane & 15))*80 + (lane >> 4)*16;
    uint32_t kaddr = sb + AK + (kwarp*80 + (lane & 15))*80 + (lane >> 4)*16;
    // PV warp mapping: mdh (dh 16-rows), nq (q 16-cols), kh (key half)
    int kh = warp & 1, nq = (warp >> 1) & 1, mdh = warp >> 2;
    uint32_t vaddr = sb + AVT + (mdh*16 + (lane & 15))*656 + (lane >> 4)*16 + kh*320;
    uint32_t paddr = sb + AP  + (nq*16  + (lane & 15))*656 + (lane >> 4)*16 + kh*320;
    float* Osk = kh ? Os1 : Os0;

    const float scale = 0.17677669529663687f;  // 1/sqrt(32)
    int r_lo = lane >> 2, cp = (lane & 3) * 2;

    #pragma unroll 1
    for (int t = 0; t < 10; t++) {
        {   // stage Q tile 32x32: plain fp16 copy
            int q = tid >> 3, d0 = (tid & 7) * 4;
            *(uint2*)(smem + AQ + q*80 + d0*2) =
                *(const uint2*)(g_Qh + rowbase + (size_t)(t*32 + q)*DD + d0);
        }
        __syncthreads();

        // ---- S = Q K^T (m16 x n80 per warp) ----
        float acc[10][4];
        #pragma unroll
        for (int g = 0; g < 10; g++)
            #pragma unroll
            for (int e = 0; e < 4; e++) acc[g][e] = 0.f;

        uint32_t af[2][4];
        ldsm4(af[0], qaddr);
        ldsm4(af[1], qaddr + 32);

        #pragma unroll
        for (int ks = 0; ks < 2; ks++) {
            #pragma unroll
            for (int p = 0; p < 5; p++) {
                uint32_t bf[4];
                ldsm4(bf, kaddr + p*1280 + ks*32);
                mma16816h(acc[p*2+0], af[ks][0], af[ks][1], af[ks][2], af[ks][3], bf[0], bf[2]);
                mma16816h(acc[p*2+1], af[ks][0], af[ks][1], af[ks][2], af[ks][3], bf[1], bf[3]);
            }
        }

        // ---- scale + bias, softmax ----
        float mx0 = -1e30f, mx1 = -1e30f;
        #pragma unroll
        for (int g = 0; g < 10; g++) {
            int key = kwarp*80 + g*8 + cp;
            float2 bb = *(const float2*)(bs + key);
            acc[g][0] = fmaf(acc[g][0], scale, bb.x);
            acc[g][1] = fmaf(acc[g][1], scale, bb.y);
            acc[g][2] = fmaf(acc[g][2], scale, bb.x);
            acc[g][3] = fmaf(acc[g][3], scale, bb.y);
            mx0 = fmaxf(mx0, fmaxf(acc[g][0], acc[g][1]));
            mx1 = fmaxf(mx1, fmaxf(acc[g][2], acc[g][3]));
        }
        #pragma unroll
        for (int o = 1; o <= 2; o <<= 1) {
            mx0 = fmaxf(mx0, __shfl_xor_sync(0xffffffffu, mx0, o));
            mx1 = fmaxf(mx1, __shfl_xor_sync(0xffffffffu, mx1, o));
        }
        if ((lane & 3) == 0) {
            mxp[(mwarp*16 + r_lo)*4 + kwarp]     = mx0;
            mxp[(mwarp*16 + r_lo + 8)*4 + kwarp] = mx1;
        }
        __syncthreads();
        {
            float4 m4 = *(const float4*)(mxp + (mwarp*16 + r_lo)*4);
            mx0 = fmaxf(fmaxf(m4.x, m4.y), fmaxf(m4.z, m4.w));
            float4 m5 = *(const float4*)(mxp + (mwarp*16 + r_lo + 8)*4);
            mx1 = fmaxf(fmaxf(m5.x, m5.y), fmaxf(m5.z, m5.w));
        }
        float s0 = 0.f, s1 = 0.f;
        #pragma unroll
        for (int g = 0; g < 10; g++) {
            acc[g][0] = __expf(acc[g][0] - mx0);
            acc[g][1] = __expf(acc[g][1] - mx0);
            acc[g][2] = __expf(acc[g][2] - mx1);
            acc[g][3] = __expf(acc[g][3] - mx1);
            s0 += acc[g][0] + acc[g][1];
            s1 += acc[g][2] + acc[g][3];
        }
        #pragma unroll
        for (int o = 1; o <= 2; o <<= 1) {
            s0 += __shfl_xor_sync(0xffffffffu, s0, o);
            s1 += __shfl_xor_sync(0xffffffffu, s1, o);
        }
        if ((lane & 3) == 0) {
            smp[(mwarp*16 + r_lo)*4 + kwarp]     = s0;
            smp[(mwarp*16 + r_lo + 8)*4 + kwarp] = s1;
        }
        __syncthreads();
        float inv0, inv1;
        {
            float4 m4 = *(const float4*)(smp + (mwarp*16 + r_lo)*4);
            inv0 = 1.f / (m4.x + m4.y + m4.z + m4.w);
            float4 m5 = *(const float4*)(smp + (mwarp*16 + r_lo + 8)*4);
            inv1 = 1.f / (m5.x + m5.y + m5.z + m5.w);
        }
        // ---- P store (fp16) ----
        int row0 = mwarp*16 + r_lo, row1 = row0 + 8;
        #pragma unroll
        for (int g = 0; g < 10; g++) {
            int key = kwarp*80 + g*8 + cp;
            *(uint32_t*)(smem + AP + row0*656 + key*2) = pack_h2(acc[g][0]*inv0, acc[g][1]*inv0);
            *(uint32_t*)(smem + AP + row1*656 + key*2) = pack_h2(acc[g][2]*inv1, acc[g][3]*inv1);
        }
        __syncthreads();

        // ---- O^T = Vt @ P^T (m16dh x n16q per warp, half keys) ----
        float acc2[2][4];
        #pragma unroll
        for (int j = 0; j < 2; j++)
            #pragma unroll
            for (int e = 0; e < 4; e++) acc2[j][e] = 0.f;

        #pragma unroll
        for (int ks = 0; ks < 10; ks++) {
            uint32_t vf[4], pf[4];
            ldsm4(vf, vaddr + ks*32);
            ldsm4(pf, paddr + ks*32);
            mma16816h(acc2[0], vf[0], vf[1], vf[2], vf[3], pf[0], pf[2]);
            mma16816h(acc2[1], vf[0], vf[1], vf[2], vf[3], pf[1], pf[3]);
        }
        #pragma unroll
        for (int j = 0; j < 2; j++) {
            int qq = nq*16 + j*8 + cp;
            int dh = mdh*16 + r_lo;
            *(float2*)(Osk + dh*34 + qq)     = make_float2(acc2[j][0], acc2[j][1]);
            *(float2*)(Osk + (dh+8)*34 + qq) = make_float2(acc2[j][2], acc2[j][3]);
        }
        __syncthreads();

        // ---- combine halves, gate (fp16), write fp16 ----
        {
            int q = tid >> 3, d0 = (tid & 7) * 4;
            size_t gb = rowbase + (size_t)(t*32 + q)*DD + d0;
            uint2 gv2 = *(const uint2*)(g_Gh + gb);
            __half2 g01 = *(__half2*)&gv2.x;
            __half2 g23 = *(__half2*)&gv2.y;
            float rx = (Os0[(d0+0)*34 + q] + Os1[(d0+0)*34 + q]) * __low2float(g01);
            float ry = (Os0[(d0+1)*34 + q] + Os1[(d0+1)*34 + q]) * __high2float(g01);
            float rz = (Os0[(d0+2)*34 + q] + Os1[(d0+2)*34 + q]) * __low2float(g23);
            float rw = (Os0[(d0+3)*34 + q] + Os1[(d0+3)*34 + q]) * __high2float(g23);
            uint2 res;
            res.x = pack_h2(rx, ry);
            res.y = pack_h2(rz, rw);
            *(uint2*)(g_Ah + gb) = res;
        }
        __syncthreads();
    }
}

// ---------------------------------------------------------------------------
// Kernel 3 (HMMA fp16): out = pair + g_Ah @ Wo^T + bo. Chunked W -> 3 CTAs/SM.
// ---------------------------------------------------------------------------
__global__ void __launch_bounds__(256, 3) oproj_mma(
    const float* __restrict__ pair, const float* __restrict__ Wo,
    const float* __restrict__ bo, float* __restrict__ out)
{
    extern __shared__ char smem[];
    uint32_t sb = smem_u32(smem);
    float* bos = (float*)(smem + MISC_OFF);

    int tid = threadIdx.x, warp = tid >> 5, lane = tid & 31;
    int r0 = blockIdx.x * 128;

    if (tid < 128) bos[tid] = bo[tid];

    // A: plain fp16 copy from g_Ah (FIXED stride: 16 uint4 chunks of 8 halves per row)
    for (int idx = tid; idx < 1024; idx += 256) {
        int r = idx >> 4, d0 = (idx & 15) * 8;
        *(uint4*)(smem + A_OFF + r*PITCHB + d0*2) =
            *(const uint4*)(g_Ah + (size_t)(r0 + r)*DD + d0);
        *(uint4*)(smem + A_OFF + (r+64)*PITCHB + d0*2) =
            *(const uint4*)(g_Ah + (size_t)(r0 + r + 64)*DD + d0);
    }
    __syncthreads();

    int wr = warp & 3, wc = warp >> 2;
    uint32_t aaddr = sb + A_OFF + (wr*32 + (lane & 15))*PITCHB + (lane >> 4)*16;
    uint32_t baddr = sb + W_OFF + (wc*32 + (lane & 15))*PITCHB + (lane >> 4)*16;
    int r_lo = lane >> 2, cp = (lane & 3) * 2;

    const float4* W4 = (const float4*)Wo;
    #pragma unroll 1
    for (int ch = 0; ch < 2; ch++) {
        int c0 = ch * 64;
        for (int idx = tid; idx < 2048; idx += 256) {
            int c = idx >> 5, dq = idx & 31, d0 = dq * 4;
            float4 w = W4[(c0 + c)*32 + dq];
            uint2 hh;
            hh.x = pack_h2(w.x, w.y);
            hh.y = pack_h2(w.z, w.w);
            *(uint2*)(smem + W_OFF + c*PITCHB + d0*2) = hh;
        }
        __syncthreads();

        float acc[2][4][4];
        #pragma unroll
        for (int mt = 0; mt < 2; mt++)
            #pragma unroll
            for (int nt = 0; nt < 4; nt++)
                #pragma unroll
                for (int e = 0; e < 4; e++) acc[mt][nt][e] = 0.f;

        #pragma unroll
        for (int ks = 0; ks < 8; ks++) {
            uint32_t af0[4], af1[4];
            ldsm4(af0, aaddr + ks*32);
            ldsm4(af1, aaddr + 16*PITCHB + ks*32);
            #pragma unroll
            for (int ntp = 0; ntp < 2; ntp++) {
                uint32_t bf[4];
                ldsm4(bf, baddr + ntp*16*PITCHB + ks*32);
                mma16816h(acc[0][ntp*2+0], af0[0], af0[1], af0[2], af0[3], bf[0], bf[2]);
                mma16816h(acc[0][ntp*2+1], af0[0], af0[1], af0[2], af0[3], bf[1], bf[3]);
                mma16816h(acc[1][ntp*2+0], af1[0], af1[1], af1[2], af1[3], bf[0], bf[2]);
                mma16816h(acc[1][ntp*2+1], af1[0], af1[1], af1[2], af1[3], bf[1], bf[3]);
            }
        }

        #pragma unroll
        for (int mt = 0; mt < 2; mt++) {
            int row = r0 + wr*32 + mt*16 + r_lo;
            #pragma unroll
            for (int nt = 0; nt < 4; nt++) {
                int col = c0 + wc*32 + nt*8 + cp;
                size_t g0 = (size_t)row*DD + col;
                size_t g1 = (size_t)(row+8)*DD + col;
                float2 p0 = *(const float2*)(pair + g0);
                float2 p1 = *(const float2*)(pair + g1);
                *(float2*)(out + g0) = make_float2(p0.x + bos[col]   + acc[mt][nt][0],
                                                   p0.y + bos[col+1] + acc[mt][nt][1]);
                *(float2*)(out + g1) = make_float2(p1.x + bos[col]   + acc[mt][nt][2],
                                                   p1.y + bos[col+1] + acc[mt][nt][3]);
            }
        }
        __syncthreads();
    }
}

// ---------------------------------------------------------------------------
extern "C" void kernel_launch(void* const* d_in, const int* in_sizes, int n_in,
                              void* d_out, int out_size)
{
    const float* pair = (const float*)d_in[0];
    const float* nw   = (const float*)d_in[1];
    const float* nb   = (const float*)d_in[2];
    const float* Wq   = (const float*)d_in[3];
    const float* Wk   = (const float*)d_in[4];
    const float* Wv   = (const float*)d_in[5];
    const float* Wg   = (const float*)d_in[6];
    const float* bg   = (const float*)d_in[7];
    const float* Wo   = (const float*)d_in[8];
    const float* bo   = (const float*)d_in[9];
    const float* Wb   = (const float*)d_in[10];
    float* out = (float*)d_out;

    size_t sm1 = MISC_OFF + 3584;     // 55808 B ~ 54.5 KB
    size_t sm2 = ASMEM_TOTAL;         // 81152 B ~ 79.3 KB -> 2 CTAs/SM
    size_t sm3 = MISC_OFF + 512;      // 52736 B ~ 51.5 KB

    cudaFuncSetAttribute(ln_proj_mma, cudaFuncAttributeMaxDynamicSharedMemorySize, (int)sm1);
    cudaFuncSetAttribute(attn_mma,    cudaFuncAttributeMaxDynamicSharedMemorySize, (int)sm2);
    cudaFuncSetAttribute(oproj_mma,   cudaFuncAttributeMaxDynamicSharedMemorySize, (int)sm3);

    ln_proj_mma<<<NR/128, 256, sm1>>>(pair, nw, nb, Wq, Wk, Wv, Wg, bg, Wb);
    attn_mma<<<dim3(NH, LL), 256, sm2>>>();
    oproj_mma<<<NR/128, 256, sm3>>>(pair, Wo, bo, out);
}